// round 1
// baseline (speedup 1.0000x reference)
#include <cuda_runtime.h>
#include <cstdint>

// Problem constants (fixed by the dataset)
#define Bc 4
#define Tc 2048
#define Vc 512
#define Cc 512
#define Hc 4
#define Dc 128
#define NBc 128          // 2*NB
#define MROWS (Bc*Tc)    // 8192

// Scratch (device globals — no allocation allowed)
__device__ float g_vw[Vc*Cc];
__device__ float g_ow[Vc*Cc];
__device__ float g_q[MROWS*Cc];
__device__ float g_k[MROWS*Cc];
__device__ float g_v[MROWS*Cc];
__device__ float g_r[MROWS*Cc];

// ---------------------------------------------------------------------------
// Generic 128x128x8 fp32 GEMM tile body. C[M,N] = alpha * A[M,K] @ op(B)
// TB=false: B is [K,N] row-major (NN).  TB=true: B is [N,K] row-major (NT).
// M,N multiples of 128; K multiple of 8. 256 threads, 8x8 microtile/thread.
// ---------------------------------------------------------------------------
template <bool TB>
__device__ __forceinline__ void sgemm_body(
    const float* __restrict__ A, const float* __restrict__ B,
    float* __restrict__ C, int M, int N, int K, float alpha, int bx, int by)
{
    __shared__ float As[8][132];
    __shared__ float Bs[8][132];
    const int tid = threadIdx.x;
    const int tx = tid & 15, ty = tid >> 4;

    float acc[8][8];
#pragma unroll
    for (int i = 0; i < 8; i++)
#pragma unroll
        for (int j = 0; j < 8; j++) acc[i][j] = 0.f;

    const float* Ab = A + (size_t)(by * 128) * K;

    for (int k0 = 0; k0 < K; k0 += 8) {
        // Load A tile (128 rows x 8 k), transposed into As[k][m]
        {
            const int ar = tid >> 1, ac = (tid & 1) * 4;
            float4 v = *(const float4*)(Ab + (size_t)ar * K + k0 + ac);
            As[ac + 0][ar] = v.x; As[ac + 1][ar] = v.y;
            As[ac + 2][ar] = v.z; As[ac + 3][ar] = v.w;
        }
        if (TB) {
            const int br = tid >> 1, bc = (tid & 1) * 4;
            float4 v = *(const float4*)(B + (size_t)(bx * 128 + br) * K + k0 + bc);
            Bs[bc + 0][br] = v.x; Bs[bc + 1][br] = v.y;
            Bs[bc + 2][br] = v.z; Bs[bc + 3][br] = v.w;
        } else {
            const int br = tid >> 5, bc = (tid & 31) * 4;
            float4 v = *(const float4*)(B + (size_t)(k0 + br) * N + bx * 128 + bc);
            *(float4*)&Bs[br][bc] = v;
        }
        __syncthreads();

#pragma unroll
        for (int kk = 0; kk < 8; kk++) {
            float a[8], bf[8];
            *(float4*)(a)     = *(const float4*)&As[kk][ty * 8];
            *(float4*)(a + 4) = *(const float4*)&As[kk][ty * 8 + 4];
            *(float4*)(bf)     = *(const float4*)&Bs[kk][tx * 8];
            *(float4*)(bf + 4) = *(const float4*)&Bs[kk][tx * 8 + 4];
#pragma unroll
            for (int i = 0; i < 8; i++)
#pragma unroll
                for (int j = 0; j < 8; j++) acc[i][j] += a[i] * bf[j];
        }
        __syncthreads();
    }

    float* Cb = C + (size_t)(by * 128 + ty * 8) * N + bx * 128 + tx * 8;
#pragma unroll
    for (int i = 0; i < 8; i++) {
        float4 o0, o1;
        o0.x = acc[i][0] * alpha; o0.y = acc[i][1] * alpha;
        o0.z = acc[i][2] * alpha; o0.w = acc[i][3] * alpha;
        o1.x = acc[i][4] * alpha; o1.y = acc[i][5] * alpha;
        o1.z = acc[i][6] * alpha; o1.w = acc[i][7] * alpha;
        *(float4*)(Cb + (size_t)i * N)     = o0;
        *(float4*)(Cb + (size_t)i * N + 4) = o1;
    }
}

// v_w = basis @ v_coeffs^T ; o_w = basis @ o_coeffs^T   (z selects)
__global__ void __launch_bounds__(256) k_weights(
    const float* __restrict__ basis, const float* __restrict__ vc,
    const float* __restrict__ oc)
{
    const float* Bm = (blockIdx.z == 0) ? vc : oc;
    float* Cm = (blockIdx.z == 0) ? g_vw : g_ow;
    sgemm_body<true>(basis, Bm, Cm, Vc, Cc, NBc, 1.f, blockIdx.x, blockIdx.y);
}

// q_raw = x@Wq ; k_raw = x@Wk ; v = x@v_w   (z selects)
__global__ void __launch_bounds__(256) k_proj(
    const float* __restrict__ x, const float* __restrict__ wq,
    const float* __restrict__ wk)
{
    const float* Bm = (blockIdx.z == 0) ? wq : (blockIdx.z == 1 ? wk : g_vw);
    float* Cm = (blockIdx.z == 0) ? g_q : (blockIdx.z == 1 ? g_k : g_v);
    sgemm_body<false>(x, Bm, Cm, MROWS, Cc, Cc, 1.f, blockIdx.x, blockIdx.y);
}

// In-place L2 normalization of q and k rows (512 elems each)
__global__ void __launch_bounds__(256) k_norm()
{
    const int row = blockIdx.x;
    float* q = g_q + (size_t)row * Cc;
    float* k = g_k + (size_t)row * Cc;
    const int t = threadIdx.x;
    float q0 = q[t], q1 = q[t + 256];
    float k0 = k[t], k1 = k[t + 256];
    float sq = q0 * q0 + q1 * q1;
    float sk = k0 * k0 + k1 * k1;
#pragma unroll
    for (int off = 16; off; off >>= 1) {
        sq += __shfl_xor_sync(0xffffffffu, sq, off);
        sk += __shfl_xor_sync(0xffffffffu, sk, off);
    }
    __shared__ float rq[8], rk[8];
    __shared__ float inv[2];
    const int w = t >> 5, l = t & 31;
    if (l == 0) { rq[w] = sq; rk[w] = sk; }
    __syncthreads();
    if (t == 0) {
        float a = 0.f, c = 0.f;
#pragma unroll
        for (int i = 0; i < 8; i++) { a += rq[i]; c += rk[i]; }
        inv[0] = 1.f / fmaxf(sqrtf(a), 1e-12f);
        inv[1] = 1.f / fmaxf(sqrtf(c), 1e-12f);
    }
    __syncthreads();
    const float iq = inv[0], ik = inv[1];
    q[t] = q0 * iq; q[t + 256] = q1 * iq;
    k[t] = k0 * ik; k[t + 256] = k1 * ik;
}

// ---------------------------------------------------------------------------
// Attention with anti-causal decay mask.
// Block = (qtile 64 rows, head h, batch b). Streams key tiles kb >= qt.
// retrieved[i] = sum_{j>i} decay^(j-i-1) (q_i . k_j) v_j
// ---------------------------------------------------------------------------
#define SQP 132   // padded row stride (floats) for Q/K/V tiles
#define SSP 80    // padded row stride for S tile
#define ATTN_SMEM ((3 * 64 * SQP + 64 * SSP) * 4)

__global__ void __launch_bounds__(256) k_attn(const float* __restrict__ dlog)
{
    extern __shared__ float sm[];
    float* Qs = sm;
    float* Ks = sm + 64 * SQP;
    float* Vs = sm + 2 * 64 * SQP;
    float* Ss = sm + 3 * 64 * SQP;

    const int qt = blockIdx.x;   // 0..31
    const int h  = blockIdx.y;   // 0..3
    const int b  = blockIdx.z;   // 0..3
    const int tid = threadIdx.x;
    const int tg = tid >> 4;     // 0..15 (row group)
    const int tc = tid & 15;     // 0..15 (col group)

    const float dec = 1.f / (1.f + expf(-dlog[h]));
    const float l2d = log2f(dec);

    const size_t qbase = ((size_t)b * Tc + qt * 64) * Cc + h * Dc;

    // Load Q tile (64 x 128)
    for (int i = tid; i < 64 * 32; i += 256) {
        const int r = i >> 5, c4 = i & 31;
        *(float4*)(Qs + r * SQP + c4 * 4) =
            *(const float4*)(g_q + qbase + (size_t)r * Cc + c4 * 4);
    }

    float o[4][8];
#pragma unroll
    for (int i = 0; i < 4; i++)
#pragma unroll
        for (int j = 0; j < 8; j++) o[i][j] = 0.f;

    for (int kb = qt; kb < Tc / 64; kb++) {
        __syncthreads();
        const size_t kvbase = ((size_t)b * Tc + kb * 64) * Cc + h * Dc;
        for (int i = tid; i < 64 * 32; i += 256) {
            const int r = i >> 5, c4 = i & 31;
            *(float4*)(Ks + r * SQP + c4 * 4) =
                *(const float4*)(g_k + kvbase + (size_t)r * Cc + c4 * 4);
            *(float4*)(Vs + r * SQP + c4 * 4) =
                *(const float4*)(g_v + kvbase + (size_t)r * Cc + c4 * 4);
        }
        __syncthreads();

        // S = Q K^T (64x64), thread computes strided 4x4 microtile
        float acc[4][4];
#pragma unroll
        for (int i = 0; i < 4; i++)
#pragma unroll
            for (int j = 0; j < 4; j++) acc[i][j] = 0.f;

#pragma unroll 4
        for (int kk4 = 0; kk4 < 32; kk4++) {
            float4 qv[4], kv[4];
#pragma unroll
            for (int i = 0; i < 4; i++)
                qv[i] = *(const float4*)(Qs + (tg + 16 * i) * SQP + kk4 * 4);
#pragma unroll
            for (int j = 0; j < 4; j++)
                kv[j] = *(const float4*)(Ks + (tc + 16 * j) * SQP + kk4 * 4);
#pragma unroll
            for (int i = 0; i < 4; i++)
#pragma unroll
                for (int j = 0; j < 4; j++)
                    acc[i][j] += qv[i].x * kv[j].x + qv[i].y * kv[j].y +
                                 qv[i].z * kv[j].z + qv[i].w * kv[j].w;
        }

        // Apply decay mask + store to Ss
#pragma unroll
        for (int i = 0; i < 4; i++) {
            const int ig = qt * 64 + tg + 16 * i;
#pragma unroll
            for (int j = 0; j < 4; j++) {
                const int jg = kb * 64 + tc + 16 * j;
                float wgt = 0.f;
                if (jg > ig) wgt = exp2f(l2d * (float)(jg - ig - 1));
                Ss[(tg + 16 * i) * SSP + tc + 16 * j] = acc[i][j] * wgt;
            }
        }
        __syncthreads();

        // O += S V : thread handles rows {tg+16i}, cols tc*8..tc*8+7
#pragma unroll 4
        for (int j = 0; j < 64; j++) {
            const float s0 = Ss[(tg)      * SSP + j];
            const float s1 = Ss[(tg + 16) * SSP + j];
            const float s2 = Ss[(tg + 32) * SSP + j];
            const float s3 = Ss[(tg + 48) * SSP + j];
            const float4 v0 = *(const float4*)(Vs + j * SQP + tc * 8);
            const float4 v1 = *(const float4*)(Vs + j * SQP + tc * 8 + 4);
            o[0][0] += s0 * v0.x; o[0][1] += s0 * v0.y; o[0][2] += s0 * v0.z; o[0][3] += s0 * v0.w;
            o[0][4] += s0 * v1.x; o[0][5] += s0 * v1.y; o[0][6] += s0 * v1.z; o[0][7] += s0 * v1.w;
            o[1][0] += s1 * v0.x; o[1][1] += s1 * v0.y; o[1][2] += s1 * v0.z; o[1][3] += s1 * v0.w;
            o[1][4] += s1 * v1.x; o[1][5] += s1 * v1.y; o[1][6] += s1 * v1.z; o[1][7] += s1 * v1.w;
            o[2][0] += s2 * v0.x; o[2][1] += s2 * v0.y; o[2][2] += s2 * v0.z; o[2][3] += s2 * v0.w;
            o[2][4] += s2 * v1.x; o[2][5] += s2 * v1.y; o[2][6] += s2 * v1.z; o[2][7] += s2 * v1.w;
            o[3][0] += s3 * v0.x; o[3][1] += s3 * v0.y; o[3][2] += s3 * v0.z; o[3][3] += s3 * v0.w;
            o[3][4] += s3 * v1.x; o[3][5] += s3 * v1.y; o[3][6] += s3 * v1.z; o[3][7] += s3 * v1.w;
        }
    }

    // Write O tile to g_r at [b, qt*64 + row, h*128 + col]
#pragma unroll
    for (int i = 0; i < 4; i++) {
        float4 o0, o1;
        o0.x = o[i][0]; o0.y = o[i][1]; o0.z = o[i][2]; o0.w = o[i][3];
        o1.x = o[i][4]; o1.y = o[i][5]; o1.z = o[i][6]; o1.w = o[i][7];
        float* dst = g_r + qbase + (size_t)(tg + 16 * i) * Cc + tc * 8;
        *(float4*)(dst)     = o0;
        *(float4*)(dst + 4) = o1;
    }
}

// out = retrieved @ o_w^T * out_scale
__global__ void __launch_bounds__(256) k_out(
    float* __restrict__ out, const float* __restrict__ oscale)
{
    const float al = __ldg(oscale);
    sgemm_body<true>(g_r, g_ow, out, MROWS, Vc, Cc, al, blockIdx.x, blockIdx.y);
}

extern "C" void kernel_launch(void* const* d_in, const int* in_sizes, int n_in,
                              void* d_out, int out_size)
{
    const float* x     = (const float*)d_in[0];
    const float* basis = (const float*)d_in[1];
    const float* wq    = (const float*)d_in[2];
    const float* wk    = (const float*)d_in[3];
    const float* vc    = (const float*)d_in[4];
    const float* oc    = (const float*)d_in[5];
    const float* dlog  = (const float*)d_in[6];
    const float* oscal = (const float*)d_in[7];
    float* out = (float*)d_out;

    (void)in_sizes; (void)n_in; (void)out_size;

    cudaFuncSetAttribute(k_attn, cudaFuncAttributeMaxDynamicSharedMemorySize,
                         ATTN_SMEM);

    k_weights<<<dim3(Cc / 128, Vc / 128, 2), 256>>>(basis, vc, oc);
    k_proj<<<dim3(Cc / 128, MROWS / 128, 3), 256>>>(x, wq, wk);
    k_norm<<<MROWS, 256>>>();
    k_attn<<<dim3(Tc / 64, Hc, Bc), 256, ATTN_SMEM>>>(dlog);
    k_out<<<dim3(Vc / 128, MROWS / 128), 256>>>(out, oscal);
}

// round 2
// speedup vs baseline: 1.5463x; 1.5463x over previous
#include <cuda_runtime.h>
#include <cstdint>

// Problem constants (fixed by the dataset)
#define Bc 4
#define Tc 2048
#define Vc 512
#define Cc 512
#define Hc 4
#define Dc 128
#define NBc 128          // 2*NB
#define MROWS (Bc*Tc)    // 8192
#define NCH 32           // chunks of 64 along T
#define CHL 64           // chunk length

// Scratch (device globals — no allocation allowed)
__device__ float g_vw[Vc*Cc];
__device__ float g_ow[Vc*Cc];
__device__ float g_q[MROWS*Cc];
__device__ float g_k[MROWS*Cc];
__device__ float g_v[MROWS*Cc];
__device__ float g_r[MROWS*Cc];
// chunk states: [b*Hc+h][c][128][128]
__device__ float g_stA[(size_t)16*NCH*Dc*Dc];
__device__ float g_stT[(size_t)16*NCH*Dc*Dc];

// ---------------------------------------------------------------------------
// Generic 128x128x8 fp32 GEMM tile body. C[M,N] = alpha * A[M,K] @ op(B)
// ---------------------------------------------------------------------------
template <bool TB>
__device__ __forceinline__ void sgemm_body(
    const float* __restrict__ A, const float* __restrict__ B,
    float* __restrict__ C, int M, int N, int K, float alpha, int bx, int by)
{
    __shared__ float As[8][132];
    __shared__ float Bs[8][132];
    const int tid = threadIdx.x;
    const int tx = tid & 15, ty = tid >> 4;

    float acc[8][8];
#pragma unroll
    for (int i = 0; i < 8; i++)
#pragma unroll
        for (int j = 0; j < 8; j++) acc[i][j] = 0.f;

    const float* Ab = A + (size_t)(by * 128) * K;

    for (int k0 = 0; k0 < K; k0 += 8) {
        {
            const int ar = tid >> 1, ac = (tid & 1) * 4;
            float4 v = *(const float4*)(Ab + (size_t)ar * K + k0 + ac);
            As[ac + 0][ar] = v.x; As[ac + 1][ar] = v.y;
            As[ac + 2][ar] = v.z; As[ac + 3][ar] = v.w;
        }
        if (TB) {
            const int br = tid >> 1, bc = (tid & 1) * 4;
            float4 v = *(const float4*)(B + (size_t)(bx * 128 + br) * K + k0 + bc);
            Bs[bc + 0][br] = v.x; Bs[bc + 1][br] = v.y;
            Bs[bc + 2][br] = v.z; Bs[bc + 3][br] = v.w;
        } else {
            const int br = tid >> 5, bc = (tid & 31) * 4;
            float4 v = *(const float4*)(B + (size_t)(k0 + br) * N + bx * 128 + bc);
            *(float4*)&Bs[br][bc] = v;
        }
        __syncthreads();

#pragma unroll
        for (int kk = 0; kk < 8; kk++) {
            float a[8], bf[8];
            *(float4*)(a)     = *(const float4*)&As[kk][ty * 8];
            *(float4*)(a + 4) = *(const float4*)&As[kk][ty * 8 + 4];
            *(float4*)(bf)     = *(const float4*)&Bs[kk][tx * 8];
            *(float4*)(bf + 4) = *(const float4*)&Bs[kk][tx * 8 + 4];
#pragma unroll
            for (int i = 0; i < 8; i++)
#pragma unroll
                for (int j = 0; j < 8; j++) acc[i][j] += a[i] * bf[j];
        }
        __syncthreads();
    }

    float* Cb = C + (size_t)(by * 128 + ty * 8) * N + bx * 128 + tx * 8;
#pragma unroll
    for (int i = 0; i < 8; i++) {
        float4 o0, o1;
        o0.x = acc[i][0] * alpha; o0.y = acc[i][1] * alpha;
        o0.z = acc[i][2] * alpha; o0.w = acc[i][3] * alpha;
        o1.x = acc[i][4] * alpha; o1.y = acc[i][5] * alpha;
        o1.z = acc[i][6] * alpha; o1.w = acc[i][7] * alpha;
        *(float4*)(Cb + (size_t)i * N)     = o0;
        *(float4*)(Cb + (size_t)i * N + 4) = o1;
    }
}

__global__ void __launch_bounds__(256) k_weights(
    const float* __restrict__ basis, const float* __restrict__ vc,
    const float* __restrict__ oc)
{
    const float* Bm = (blockIdx.z == 0) ? vc : oc;
    float* Cm = (blockIdx.z == 0) ? g_vw : g_ow;
    sgemm_body<true>(basis, Bm, Cm, Vc, Cc, NBc, 1.f, blockIdx.x, blockIdx.y);
}

__global__ void __launch_bounds__(256) k_proj(
    const float* __restrict__ x, const float* __restrict__ wq,
    const float* __restrict__ wk)
{
    const float* Bm = (blockIdx.z == 0) ? wq : (blockIdx.z == 1 ? wk : g_vw);
    float* Cm = (blockIdx.z == 0) ? g_q : (blockIdx.z == 1 ? g_k : g_v);
    sgemm_body<false>(x, Bm, Cm, MROWS, Cc, Cc, 1.f, blockIdx.x, blockIdx.y);
}

__global__ void __launch_bounds__(256) k_norm()
{
    const int row = blockIdx.x;
    float* q = g_q + (size_t)row * Cc;
    float* k = g_k + (size_t)row * Cc;
    const int t = threadIdx.x;
    float q0 = q[t], q1 = q[t + 256];
    float k0 = k[t], k1 = k[t + 256];
    float sq = q0 * q0 + q1 * q1;
    float sk = k0 * k0 + k1 * k1;
#pragma unroll
    for (int off = 16; off; off >>= 1) {
        sq += __shfl_xor_sync(0xffffffffu, sq, off);
        sk += __shfl_xor_sync(0xffffffffu, sk, off);
    }
    __shared__ float rq[8], rk[8];
    __shared__ float inv[2];
    const int w = t >> 5, l = t & 31;
    if (l == 0) { rq[w] = sq; rk[w] = sk; }
    __syncthreads();
    if (t == 0) {
        float a = 0.f, c = 0.f;
#pragma unroll
        for (int i = 0; i < 8; i++) { a += rq[i]; c += rk[i]; }
        inv[0] = 1.f / fmaxf(sqrtf(a), 1e-12f);
        inv[1] = 1.f / fmaxf(sqrtf(c), 1e-12f);
    }
    __syncthreads();
    const float iq = inv[0], ik = inv[1];
    q[t] = q0 * iq; q[t + 256] = q1 * iq;
    k[t] = k0 * ik; k[t + 256] = k1 * ik;
}

// ---------------------------------------------------------------------------
// Phase A: per-chunk local state  A_c[d1][d2] = sum_jl d^jl * k[cL+jl][d1] * v[cL+jl][d2]
// Grid: (NCH-1, H, B) with c = x+1  (A_0 never used). 256 thr, 8x8 microtile.
// ---------------------------------------------------------------------------
#define STATE_SMEM (2 * 64 * 132 * 4)
__global__ void __launch_bounds__(256) k_state(const float* __restrict__ dlog)
{
    extern __shared__ float sm[];
    float (*Ks)[132] = (float(*)[132])sm;
    float (*Vs)[132] = (float(*)[132])(sm + 64 * 132);

    const int c = blockIdx.x + 1, h = blockIdx.y, b = blockIdx.z;
    const int tid = threadIdx.x;
    const float dec = 1.f / (1.f + expf(-dlog[h]));
    const float l2d = log2f(dec);

    const size_t base = ((size_t)b * Tc + c * CHL) * Cc + h * Dc;
    for (int i = tid; i < 64 * 32; i += 256) {
        const int r = i >> 5, c4 = i & 31;
        const float w = exp2f(l2d * (float)r);
        float4 kv = *(const float4*)(g_k + base + (size_t)r * Cc + c4 * 4);
        kv.x *= w; kv.y *= w; kv.z *= w; kv.w *= w;
        *(float4*)&Ks[r][c4 * 4] = kv;
        *(float4*)&Vs[r][c4 * 4] = *(const float4*)(g_v + base + (size_t)r * Cc + c4 * 4);
    }
    __syncthreads();

    const int tx = tid & 15, ty = tid >> 4;
    float acc[8][8];
#pragma unroll
    for (int i = 0; i < 8; i++)
#pragma unroll
        for (int j = 0; j < 8; j++) acc[i][j] = 0.f;

#pragma unroll 4
    for (int j = 0; j < 64; j++) {
        float a[8], bb[8];
        *(float4*)(a)      = *(const float4*)&Ks[j][ty * 8];
        *(float4*)(a + 4)  = *(const float4*)&Ks[j][ty * 8 + 4];
        *(float4*)(bb)     = *(const float4*)&Vs[j][tx * 8];
        *(float4*)(bb + 4) = *(const float4*)&Vs[j][tx * 8 + 4];
#pragma unroll
        for (int i = 0; i < 8; i++)
#pragma unroll
            for (int jj = 0; jj < 8; jj++) acc[i][jj] += a[i] * bb[jj];
    }

    float* dst = g_stA + ((size_t)(b * Hc + h) * NCH + c) * (Dc * Dc);
#pragma unroll
    for (int i = 0; i < 8; i++) {
        float4 o0, o1;
        o0.x = acc[i][0]; o0.y = acc[i][1]; o0.z = acc[i][2]; o0.w = acc[i][3];
        o1.x = acc[i][4]; o1.y = acc[i][5]; o1.z = acc[i][6]; o1.w = acc[i][7];
        *(float4*)(dst + (size_t)(ty * 8 + i) * Dc + tx * 8)     = o0;
        *(float4*)(dst + (size_t)(ty * 8 + i) * Dc + tx * 8 + 4) = o1;
    }
}

// ---------------------------------------------------------------------------
// Phase B: backward scan  T_{c-1} = A_c + d^64 * T_c, T_{NCH-1}=0.
// Grid: 16 blocks (b*H+h). Each thread owns 16 float4s, coalesced stride.
// ---------------------------------------------------------------------------
__global__ void __launch_bounds__(256) k_scan(const float* __restrict__ dlog)
{
    const int bh = blockIdx.x;
    const int h = bh & (Hc - 1);
    const int tid = threadIdx.x;
    const float dec = 1.f / (1.f + expf(-dlog[h]));
    const float dL = exp2f(log2f(dec) * (float)CHL);

    float4 run[16];
#pragma unroll
    for (int r = 0; r < 16; r++) run[r] = make_float4(0.f, 0.f, 0.f, 0.f);

    for (int c = NCH - 1; c >= 1; c--) {
        const float4* A = (const float4*)(g_stA + ((size_t)bh * NCH + c) * (Dc * Dc));
        float4* Tt = (float4*)(g_stT + ((size_t)bh * NCH + (c - 1)) * (Dc * Dc));
#pragma unroll
        for (int r = 0; r < 16; r++) {
            float4 a = A[r * 256 + tid];
            run[r].x = a.x + dL * run[r].x;
            run[r].y = a.y + dL * run[r].y;
            run[r].z = a.z + dL * run[r].z;
            run[r].w = a.w + dL * run[r].w;
            Tt[r * 256 + tid] = run[r];
        }
    }
}

// ---------------------------------------------------------------------------
// Phase C: chunk attention.
//   intra: masked 64x64 QK^T (weight d^(jl-il-1), jl>il) then S@V
//   inter: o[il] += d^(63-il) * q_il @ T_c    (T streamed through Ks buffer)
// ---------------------------------------------------------------------------
#define SQP 132
#define SSP 80
#define CATTN_SMEM ((3 * 64 * SQP + 64 * SSP) * 4)

__global__ void __launch_bounds__(256) k_cattn(const float* __restrict__ dlog)
{
    extern __shared__ float sm[];
    float* Qs = sm;
    float* Ks = sm + 64 * SQP;
    float* Vs = sm + 2 * 64 * SQP;
    float* Ss = sm + 3 * 64 * SQP;

    const int c = blockIdx.x;    // 0..31
    const int h = blockIdx.y;
    const int b = blockIdx.z;
    const int tid = threadIdx.x;
    const int tg = tid >> 4;     // 0..15
    const int tc = tid & 15;     // 0..15

    const float dec = 1.f / (1.f + expf(-dlog[h]));
    const float l2d = log2f(dec);

    const size_t qbase = ((size_t)b * Tc + c * CHL) * Cc + h * Dc;

    for (int i = tid; i < 64 * 32; i += 256) {
        const int r = i >> 5, c4 = i & 31;
        *(float4*)(Qs + r * SQP + c4 * 4) =
            *(const float4*)(g_q + qbase + (size_t)r * Cc + c4 * 4);
        *(float4*)(Ks + r * SQP + c4 * 4) =
            *(const float4*)(g_k + qbase + (size_t)r * Cc + c4 * 4);
        *(float4*)(Vs + r * SQP + c4 * 4) =
            *(const float4*)(g_v + qbase + (size_t)r * Cc + c4 * 4);
    }
    __syncthreads();

    // --- intra: S = Q K^T, 4x4 strided microtile per thread ---
    float acc[4][4];
#pragma unroll
    for (int i = 0; i < 4; i++)
#pragma unroll
        for (int j = 0; j < 4; j++) acc[i][j] = 0.f;

#pragma unroll 4
    for (int kk4 = 0; kk4 < 32; kk4++) {
        float4 qv[4], kv[4];
#pragma unroll
        for (int i = 0; i < 4; i++)
            qv[i] = *(const float4*)(Qs + (tg + 16 * i) * SQP + kk4 * 4);
#pragma unroll
        for (int j = 0; j < 4; j++)
            kv[j] = *(const float4*)(Ks + (tc + 16 * j) * SQP + kk4 * 4);
#pragma unroll
        for (int i = 0; i < 4; i++)
#pragma unroll
            for (int j = 0; j < 4; j++)
                acc[i][j] += qv[i].x * kv[j].x + qv[i].y * kv[j].y +
                             qv[i].z * kv[j].z + qv[i].w * kv[j].w;
    }

#pragma unroll
    for (int i = 0; i < 4; i++) {
        const int il = tg + 16 * i;
#pragma unroll
        for (int j = 0; j < 4; j++) {
            const int jl = tc + 16 * j;
            float wgt = 0.f;
            if (jl > il) wgt = exp2f(l2d * (float)(jl - il - 1));
            Ss[il * SSP + jl] = acc[i][j] * wgt;
        }
    }
    __syncthreads();

    float o[4][8];
#pragma unroll
    for (int i = 0; i < 4; i++)
#pragma unroll
        for (int j = 0; j < 8; j++) o[i][j] = 0.f;

    // --- intra: O += S V ---
#pragma unroll 4
    for (int j = 0; j < 64; j++) {
        const float s0 = Ss[(tg)      * SSP + j];
        const float s1 = Ss[(tg + 16) * SSP + j];
        const float s2 = Ss[(tg + 32) * SSP + j];
        const float s3 = Ss[(tg + 48) * SSP + j];
        const float4 v0 = *(const float4*)(Vs + j * SQP + tc * 8);
        const float4 v1 = *(const float4*)(Vs + j * SQP + tc * 8 + 4);
        o[0][0] += s0 * v0.x; o[0][1] += s0 * v0.y; o[0][2] += s0 * v0.z; o[0][3] += s0 * v0.w;
        o[0][4] += s0 * v1.x; o[0][5] += s0 * v1.y; o[0][6] += s0 * v1.z; o[0][7] += s0 * v1.w;
        o[1][0] += s1 * v0.x; o[1][1] += s1 * v0.y; o[1][2] += s1 * v0.z; o[1][3] += s1 * v0.w;
        o[1][4] += s1 * v1.x; o[1][5] += s1 * v1.y; o[1][6] += s1 * v1.z; o[1][7] += s1 * v1.w;
        o[2][0] += s2 * v0.x; o[2][1] += s2 * v0.y; o[2][2] += s2 * v0.z; o[2][3] += s2 * v0.w;
        o[2][4] += s2 * v1.x; o[2][5] += s2 * v1.y; o[2][6] += s2 * v1.z; o[2][7] += s2 * v1.w;
        o[3][0] += s3 * v0.x; o[3][1] += s3 * v0.y; o[3][2] += s3 * v0.z; o[3][3] += s3 * v0.w;
        o[3][4] += s3 * v1.x; o[3][5] += s3 * v1.y; o[3][6] += s3 * v1.z; o[3][7] += s3 * v1.w;
    }

    // --- inter: O[il] += d^(63-il) * q_il @ T_c  (stream T through Ks) ---
    if (c < NCH - 1) {
        float f[4];
#pragma unroll
        for (int i = 0; i < 4; i++)
            f[i] = exp2f(l2d * (float)(63 - (tg + 16 * i)));

        const float* Tsrc = g_stT + ((size_t)(b * Hc + h) * NCH + c) * (Dc * Dc);
        for (int d0 = 0; d0 < 128; d0 += 32) {
            __syncthreads();
            for (int i = tid; i < 32 * 32; i += 256) {
                const int r = i >> 5, c4 = i & 31;
                *(float4*)(Ks + r * SQP + c4 * 4) =
                    *(const float4*)(Tsrc + (size_t)(d0 + r) * Dc + c4 * 4);
            }
            __syncthreads();
#pragma unroll 8
            for (int dd = 0; dd < 32; dd++) {
                const float q0 = Qs[(tg)      * SQP + d0 + dd] * f[0];
                const float q1 = Qs[(tg + 16) * SQP + d0 + dd] * f[1];
                const float q2 = Qs[(tg + 32) * SQP + d0 + dd] * f[2];
                const float q3 = Qs[(tg + 48) * SQP + d0 + dd] * f[3];
                const float4 t0 = *(const float4*)(Ks + dd * SQP + tc * 8);
                const float4 t1 = *(const float4*)(Ks + dd * SQP + tc * 8 + 4);
                o[0][0] += q0 * t0.x; o[0][1] += q0 * t0.y; o[0][2] += q0 * t0.z; o[0][3] += q0 * t0.w;
                o[0][4] += q0 * t1.x; o[0][5] += q0 * t1.y; o[0][6] += q0 * t1.z; o[0][7] += q0 * t1.w;
                o[1][0] += q1 * t0.x; o[1][1] += q1 * t0.y; o[1][2] += q1 * t0.z; o[1][3] += q1 * t0.w;
                o[1][4] += q1 * t1.x; o[1][5] += q1 * t1.y; o[1][6] += q1 * t1.z; o[1][7] += q1 * t1.w;
                o[2][0] += q2 * t0.x; o[2][1] += q2 * t0.y; o[2][2] += q2 * t0.z; o[2][3] += q2 * t0.w;
                o[2][4] += q2 * t1.x; o[2][5] += q2 * t1.y; o[2][6] += q2 * t1.z; o[2][7] += q2 * t1.w;
                o[3][0] += q3 * t0.x; o[3][1] += q3 * t0.y; o[3][2] += q3 * t0.z; o[3][3] += q3 * t0.w;
                o[3][4] += q3 * t1.x; o[3][5] += q3 * t1.y; o[3][6] += q3 * t1.z; o[3][7] += q3 * t1.w;
            }
        }
    }

    // Write O tile
#pragma unroll
    for (int i = 0; i < 4; i++) {
        float4 o0, o1;
        o0.x = o[i][0]; o0.y = o[i][1]; o0.z = o[i][2]; o0.w = o[i][3];
        o1.x = o[i][4]; o1.y = o[i][5]; o1.z = o[i][6]; o1.w = o[i][7];
        float* dst = g_r + qbase + (size_t)(tg + 16 * i) * Cc + tc * 8;
        *(float4*)(dst)     = o0;
        *(float4*)(dst + 4) = o1;
    }
}

__global__ void __launch_bounds__(256) k_out(
    float* __restrict__ out, const float* __restrict__ oscale)
{
    const float al = __ldg(oscale);
    sgemm_body<true>(g_r, g_ow, out, MROWS, Vc, Cc, al, blockIdx.x, blockIdx.y);
}

extern "C" void kernel_launch(void* const* d_in, const int* in_sizes, int n_in,
                              void* d_out, int out_size)
{
    const float* x     = (const float*)d_in[0];
    const float* basis = (const float*)d_in[1];
    const float* wq    = (const float*)d_in[2];
    const float* wk    = (const float*)d_in[3];
    const float* vc    = (const float*)d_in[4];
    const float* oc    = (const float*)d_in[5];
    const float* dlog  = (const float*)d_in[6];
    const float* oscal = (const float*)d_in[7];
    float* out = (float*)d_out;

    (void)in_sizes; (void)n_in; (void)out_size;

    static int attr_done = 0;
    cudaFuncSetAttribute(k_state, cudaFuncAttributeMaxDynamicSharedMemorySize,
                         STATE_SMEM);
    cudaFuncSetAttribute(k_cattn, cudaFuncAttributeMaxDynamicSharedMemorySize,
                         CATTN_SMEM);
    (void)attr_done;

    k_weights<<<dim3(Cc / 128, Vc / 128, 2), 256>>>(basis, vc, oc);
    k_proj<<<dim3(Cc / 128, MROWS / 128, 3), 256>>>(x, wq, wk);
    k_norm<<<MROWS, 256>>>();
    k_state<<<dim3(NCH - 1, Hc, Bc), 256, STATE_SMEM>>>(dlog);
    k_scan<<<16, 256>>>(dlog);
    k_cattn<<<dim3(NCH, Hc, Bc), 256, CATTN_SMEM>>>(dlog);
    k_out<<<dim3(Vc / 128, MROWS / 128), 256>>>(out, oscal);
}

// round 4
// speedup vs baseline: 2.4249x; 1.5682x over previous
#include <cuda_runtime.h>
#include <cuda_bf16.h>
#include <cstdint>

// Problem constants (fixed by the dataset)
#define Bc 4
#define Tc 2048
#define Vc 512
#define Cc 512
#define Hc 4
#define Dc 128
#define NBc 128          // 2*NB
#define MROWS (Bc*Tc)    // 8192
#define NCH 32           // chunks of 64 along T
#define CHL 64           // chunk length

// fp32 scratch
__device__ float g_vw[Vc*Cc];
__device__ float g_ow[Vc*Cc];
__device__ float g_q[MROWS*Cc];
__device__ float g_k[MROWS*Cc];
__device__ float g_v[MROWS*Cc];
__device__ float g_r[MROWS*Cc];
__device__ float g_stA[(size_t)16*NCH*Dc*Dc];
__device__ float g_stT[(size_t)16*NCH*Dc*Dc];

// bf16 split scratch (hi/lo)
__device__ __nv_bfloat16 g_xh[MROWS*Cc],  g_xl[MROWS*Cc];
__device__ __nv_bfloat16 g_rh[MROWS*Cc],  g_rl[MROWS*Cc];
__device__ __nv_bfloat16 g_wqTh[Cc*Vc],   g_wqTl[Cc*Vc];
__device__ __nv_bfloat16 g_wkTh[Cc*Vc],   g_wkTl[Cc*Vc];
__device__ __nv_bfloat16 g_vwTh[Cc*Vc],   g_vwTl[Cc*Vc];
__device__ __nv_bfloat16 g_owh[Vc*Cc],    g_owl[Vc*Cc];

// ===========================================================================
// Helpers
// ===========================================================================
__device__ __forceinline__ uint32_t smem_u32(const void* p) {
    uint32_t a;
    asm("{ .reg .u64 t; cvta.to.shared.u64 t, %1; cvt.u32.u64 %0, t; }"
        : "=r"(a) : "l"(p));
    return a;
}
__device__ __forceinline__ void ldm_x4(uint32_t* r, uint32_t addr) {
    asm volatile("ldmatrix.sync.aligned.m8n8.x4.shared.b16 {%0,%1,%2,%3}, [%4];"
                 : "=r"(r[0]), "=r"(r[1]), "=r"(r[2]), "=r"(r[3]) : "r"(addr));
}
__device__ __forceinline__ void mma_bf16(float* c, const uint32_t* a,
                                         const uint32_t* b) {
    asm volatile(
        "mma.sync.aligned.m16n8k16.row.col.f32.bf16.bf16.f32 "
        "{%0,%1,%2,%3}, {%4,%5,%6,%7}, {%8,%9}, {%0,%1,%2,%3};"
        : "+f"(c[0]), "+f"(c[1]), "+f"(c[2]), "+f"(c[3])
        : "r"(a[0]), "r"(a[1]), "r"(a[2]), "r"(a[3]), "r"(b[0]), "r"(b[1]));
}

// ===========================================================================
// bf16 split-precision warp-MMA GEMM: C tile[128,128] = A[M,512] @ B[N,512]^T
// A,B pre-split (hi,lo) bf16 row-major ld=512. 3 passes: AhBh + AhBl + AlBh.
// smem slabs: 128 rows x 64 k bf16, row pitch 144B (conflict-free ldmatrix).
// 8 warps: warp tile 64x32 (wm=wid>>2, wn=wid&3).
// ===========================================================================
#define SLAB 18432                 // 128 * 144
#define GS_BYTES (4 * SLAB)        // 73728

__device__ __forceinline__ void gemm_mma_tile(
    const __nv_bfloat16* __restrict__ Ah, const __nv_bfloat16* __restrict__ Al,
    const __nv_bfloat16* __restrict__ Bh, const __nv_bfloat16* __restrict__ Bl,
    float* __restrict__ Cp, float alpha, int tm, int tn)
{
    extern __shared__ __align__(16) char smc[];
    const int tid = threadIdx.x, lane = tid & 31, wid = tid >> 5;
    const int wm = wid >> 2, wn = wid & 3;
    const uint32_t sb = smem_u32(smc);

    float acc[4][4][4];
#pragma unroll
    for (int i = 0; i < 4; i++)
#pragma unroll
        for (int j = 0; j < 4; j++)
#pragma unroll
            for (int q = 0; q < 4; q++) acc[i][j][q] = 0.f;

    // copy indices (uint4 granularity): row = idx>>3, q16 = idx&7
    const int crow = tid >> 3, cq = tid & 7;

    // ldmatrix base addresses (per-lane)
    // A: row = wm*64 + mi*16 + (lane&15), k = k0 + (lane>>4)*8
    const uint32_t a_lrow = wm * 64 + (lane & 15);
    const uint32_t a_koff = (lane >> 4) * 8;
    // B: row = wn*32 + nf*16 + (lane&7) + ((lane>>4)<<3), k = k0 + ((lane>>3)&1)*8
    const uint32_t b_lrow = wn * 32 + (lane & 7) + ((lane >> 4) << 3);
    const uint32_t b_koff = ((lane >> 3) & 1) * 8;

    for (int c = 0; c < 8; c++) {
        if (c) __syncthreads();
        const __nv_bfloat16* sA_h = Ah + ((size_t)tm * 128) * 512 + c * 64;
        const __nv_bfloat16* sA_l = Al + ((size_t)tm * 128) * 512 + c * 64;
        const __nv_bfloat16* sB_h = Bh + ((size_t)tn * 128) * 512 + c * 64;
        const __nv_bfloat16* sB_l = Bl + ((size_t)tn * 128) * 512 + c * 64;
#pragma unroll
        for (int i = 0; i < 4; i++) {
            const int row = crow + 32 * i;
            const size_t so = (size_t)row * 64 + cq;
            const uint32_t doff = row * 144 + cq * 16;
            *(uint4*)(smc + 0 * SLAB + doff) = __ldg((const uint4*)sA_h + so);
            *(uint4*)(smc + 1 * SLAB + doff) = __ldg((const uint4*)sA_l + so);
            *(uint4*)(smc + 2 * SLAB + doff) = __ldg((const uint4*)sB_h + so);
            *(uint4*)(smc + 3 * SLAB + doff) = __ldg((const uint4*)sB_l + so);
        }
        __syncthreads();

#pragma unroll
        for (int ks = 0; ks < 4; ks++) {
            const int k0 = ks * 16;
            uint32_t bh[8], bl[8];
#pragma unroll
            for (int nf = 0; nf < 2; nf++) {
                const uint32_t boff =
                    (b_lrow + nf * 16) * 144 + (k0 + b_koff) * 2;
                ldm_x4(bh + nf * 4, sb + 2 * SLAB + boff);
                ldm_x4(bl + nf * 4, sb + 3 * SLAB + boff);
            }
            // pass 1+2: Ahi*Bhi, Ahi*Blo
#pragma unroll
            for (int mi = 0; mi < 4; mi++) {
                uint32_t a[4];
                const uint32_t aoff =
                    (a_lrow + mi * 16) * 144 + (k0 + a_koff) * 2;
                ldm_x4(a, sb + 0 * SLAB + aoff);
#pragma unroll
                for (int ni = 0; ni < 4; ni++) {
                    mma_bf16(acc[mi][ni], a, bh + ni * 2);
                    mma_bf16(acc[mi][ni], a, bl + ni * 2);
                }
            }
            // pass 3: Alo*Bhi
#pragma unroll
            for (int mi = 0; mi < 4; mi++) {
                uint32_t a[4];
                const uint32_t aoff =
                    (a_lrow + mi * 16) * 144 + (k0 + a_koff) * 2;
                ldm_x4(a, sb + 1 * SLAB + aoff);
#pragma unroll
                for (int ni = 0; ni < 4; ni++)
                    mma_bf16(acc[mi][ni], a, bh + ni * 2);
            }
        }
    }

    // Epilogue: c0/c1 -> (m, n..n+1), c2/c3 -> (m+8, n..n+1)
    const int qr = lane >> 2, qc = lane & 3;
#pragma unroll
    for (int mi = 0; mi < 4; mi++) {
#pragma unroll
        for (int ni = 0; ni < 4; ni++) {
            const int m = tm * 128 + wm * 64 + mi * 16 + qr;
            const int n = tn * 128 + wn * 32 + ni * 8 + qc * 2;
            float2 v0, v1;
            v0.x = acc[mi][ni][0] * alpha; v0.y = acc[mi][ni][1] * alpha;
            v1.x = acc[mi][ni][2] * alpha; v1.y = acc[mi][ni][3] * alpha;
            *(float2*)(Cp + (size_t)m * 512 + n)       = v0;
            *(float2*)(Cp + (size_t)(m + 8) * 512 + n) = v1;
        }
    }
}

__global__ void __launch_bounds__(256) k_gemm_proj()
{
    const __nv_bfloat16 *Bh, *Bl; float* Cp;
    if (blockIdx.z == 0)      { Bh = g_wqTh; Bl = g_wqTl; Cp = g_q; }
    else if (blockIdx.z == 1) { Bh = g_wkTh; Bl = g_wkTl; Cp = g_k; }
    else                      { Bh = g_vwTh; Bl = g_vwTl; Cp = g_v; }
    gemm_mma_tile(g_xh, g_xl, Bh, Bl, Cp, 1.f, blockIdx.y, blockIdx.x);
}

__global__ void __launch_bounds__(256) k_gemm_out(float* __restrict__ out,
                                                  const float* __restrict__ os)
{
    gemm_mma_tile(g_rh, g_rl, g_owh, g_owl, out, __ldg(os), blockIdx.y,
                  blockIdx.x);
}

// ===========================================================================
// Split kernels
// ===========================================================================
__global__ void __launch_bounds__(256) k_split(const float* __restrict__ xin,
                                               int mode, int n4)
{
    const float* in = (mode == 0) ? xin : (mode == 1 ? g_ow : g_r);
    __nv_bfloat16* oh = (mode == 0) ? g_xh : (mode == 1 ? g_owh : g_rh);
    __nv_bfloat16* ol = (mode == 0) ? g_xl : (mode == 1 ? g_owl : g_rl);
    int i = blockIdx.x * 256 + threadIdx.x;
    if (i >= n4) return;
    float4 v = ((const float4*)in)[i];
    __nv_bfloat16 h0 = __float2bfloat16_rn(v.x), h1 = __float2bfloat16_rn(v.y);
    __nv_bfloat16 h2 = __float2bfloat16_rn(v.z), h3 = __float2bfloat16_rn(v.w);
    __nv_bfloat16 l0 = __float2bfloat16_rn(v.x - __bfloat162float(h0));
    __nv_bfloat16 l1 = __float2bfloat16_rn(v.y - __bfloat162float(h1));
    __nv_bfloat16 l2 = __float2bfloat16_rn(v.z - __bfloat162float(h2));
    __nv_bfloat16 l3 = __float2bfloat16_rn(v.w - __bfloat162float(h3));
    __nv_bfloat162 ph0; ph0.x = h0; ph0.y = h1;
    __nv_bfloat162 ph1; ph1.x = h2; ph1.y = h3;
    __nv_bfloat162 pl0; pl0.x = l0; pl0.y = l1;
    __nv_bfloat162 pl1; pl1.x = l2; pl1.y = l3;
    ((__nv_bfloat162*)oh)[2 * i]     = ph0;
    ((__nv_bfloat162*)oh)[2 * i + 1] = ph1;
    ((__nv_bfloat162*)ol)[2 * i]     = pl0;
    ((__nv_bfloat162*)ol)[2 * i + 1] = pl1;
}

// Transpose + split 512x512: out[n][k] = in[k][n]. z: 0=wq, 1=wk, 2=g_vw
__global__ void __launch_bounds__(1024) k_splitT(const float* __restrict__ wq,
                                                 const float* __restrict__ wk)
{
    __shared__ float t[32][33];
    const float* in = (blockIdx.z == 0) ? wq : (blockIdx.z == 1 ? wk : g_vw);
    __nv_bfloat16* oh = (blockIdx.z == 0) ? g_wqTh : (blockIdx.z == 1 ? g_wkTh : g_vwTh);
    __nv_bfloat16* ol = (blockIdx.z == 0) ? g_wqTl : (blockIdx.z == 1 ? g_wkTl : g_vwTl);
    const int x = blockIdx.x * 32 + threadIdx.x;
    const int y = blockIdx.y * 32 + threadIdx.y;
    t[threadIdx.y][threadIdx.x] = in[y * 512 + x];
    __syncthreads();
    const float v = t[threadIdx.x][threadIdx.y];
    const int ox = blockIdx.y * 32 + threadIdx.x;
    const int oy = blockIdx.x * 32 + threadIdx.y;
    __nv_bfloat16 h = __float2bfloat16_rn(v);
    oh[oy * 512 + ox] = h;
    ol[oy * 512 + ox] = __float2bfloat16_rn(v - __bfloat162float(h));
}

// ===========================================================================
// fp32 GEMM (kept for tiny k_weights only)
// ===========================================================================
template <bool TB>
__device__ __forceinline__ void sgemm_body(
    const float* __restrict__ A, const float* __restrict__ B,
    float* __restrict__ C, int M, int N, int K, float alpha, int bx, int by)
{
    __shared__ float As[8][132];
    __shared__ float Bs[8][132];
    const int tid = threadIdx.x;
    const int tx = tid & 15, ty = tid >> 4;

    float acc[8][8];
#pragma unroll
    for (int i = 0; i < 8; i++)
#pragma unroll
        for (int j = 0; j < 8; j++) acc[i][j] = 0.f;

    const float* Ab = A + (size_t)(by * 128) * K;

    for (int k0 = 0; k0 < K; k0 += 8) {
        {
            const int ar = tid >> 1, ac = (tid & 1) * 4;
            float4 v = *(const float4*)(Ab + (size_t)ar * K + k0 + ac);
            As[ac + 0][ar] = v.x; As[ac + 1][ar] = v.y;
            As[ac + 2][ar] = v.z; As[ac + 3][ar] = v.w;
        }
        if (TB) {
            const int br = tid >> 1, bc = (tid & 1) * 4;
            float4 v = *(const float4*)(B + (size_t)(bx * 128 + br) * K + k0 + bc);
            Bs[bc + 0][br] = v.x; Bs[bc + 1][br] = v.y;
            Bs[bc + 2][br] = v.z; Bs[bc + 3][br] = v.w;
        } else {
            const int br = tid >> 5, bc = (tid & 31) * 4;
            float4 v = *(const float4*)(B + (size_t)(k0 + br) * N + bx * 128 + bc);
            *(float4*)&Bs[br][bc] = v;
        }
        __syncthreads();

#pragma unroll
        for (int kk = 0; kk < 8; kk++) {
            float a[8], bf[8];
            *(float4*)(a)     = *(const float4*)&As[kk][ty * 8];
            *(float4*)(a + 4) = *(const float4*)&As[kk][ty * 8 + 4];
            *(float4*)(bf)     = *(const float4*)&Bs[kk][tx * 8];
            *(float4*)(bf + 4) = *(const float4*)&Bs[kk][tx * 8 + 4];
#pragma unroll
            for (int i = 0; i < 8; i++)
#pragma unroll
                for (int j = 0; j < 8; j++) acc[i][j] += a[i] * bf[j];
        }
        __syncthreads();
    }

    float* Cb = C + (size_t)(by * 128 + ty * 8) * N + bx * 128 + tx * 8;
#pragma unroll
    for (int i = 0; i < 8; i++) {
        float4 o0, o1;
        o0.x = acc[i][0] * alpha; o0.y = acc[i][1] * alpha;
        o0.z = acc[i][2] * alpha; o0.w = acc[i][3] * alpha;
        o1.x = acc[i][4] * alpha; o1.y = acc[i][5] * alpha;
        o1.z = acc[i][6] * alpha; o1.w = acc[i][7] * alpha;
        *(float4*)(Cb + (size_t)i * N)     = o0;
        *(float4*)(Cb + (size_t)i * N + 4) = o1;
    }
}

__global__ void __launch_bounds__(256) k_weights(
    const float* __restrict__ basis, const float* __restrict__ vc,
    const float* __restrict__ oc)
{
    const float* Bm = (blockIdx.z == 0) ? vc : oc;
    float* Cm = (blockIdx.z == 0) ? g_vw : g_ow;
    sgemm_body<true>(basis, Bm, Cm, Vc, Cc, NBc, 1.f, blockIdx.x, blockIdx.y);
}

__global__ void __launch_bounds__(256) k_norm()
{
    const int row = blockIdx.x;
    float* q = g_q + (size_t)row * Cc;
    float* k = g_k + (size_t)row * Cc;
    const int t = threadIdx.x;
    float q0 = q[t], q1 = q[t + 256];
    float k0 = k[t], k1 = k[t + 256];
    float sq = q0 * q0 + q1 * q1;
    float sk = k0 * k0 + k1 * k1;
#pragma unroll
    for (int off = 16; off; off >>= 1) {
        sq += __shfl_xor_sync(0xffffffffu, sq, off);
        sk += __shfl_xor_sync(0xffffffffu, sk, off);
    }
    __shared__ float rq[8], rk[8];
    __shared__ float inv[2];
    const int w = t >> 5, l = t & 31;
    if (l == 0) { rq[w] = sq; rk[w] = sk; }
    __syncthreads();
    if (t == 0) {
        float a = 0.f, c = 0.f;
#pragma unroll
        for (int i = 0; i < 8; i++) { a += rq[i]; c += rk[i]; }
        inv[0] = 1.f / fmaxf(sqrtf(a), 1e-12f);
        inv[1] = 1.f / fmaxf(sqrtf(c), 1e-12f);
    }
    __syncthreads();
    const float iq = inv[0], ik = inv[1];
    q[t] = q0 * iq; q[t + 256] = q1 * iq;
    k[t] = k0 * ik; k[t + 256] = k1 * ik;
}

// ---------------------------------------------------------------------------
// Phase A: per-chunk local state (fp32)
// ---------------------------------------------------------------------------
#define STATE_SMEM (2 * 64 * 132 * 4)
__global__ void __launch_bounds__(256) k_state(const float* __restrict__ dlog)
{
    extern __shared__ float sm[];
    float (*Ks)[132] = (float(*)[132])sm;
    float (*Vs)[132] = (float(*)[132])(sm + 64 * 132);

    const int c = blockIdx.x + 1, h = blockIdx.y, b = blockIdx.z;
    const int tid = threadIdx.x;
    const float dec = 1.f / (1.f + expf(-dlog[h]));
    const float l2d = log2f(dec);

    const size_t base = ((size_t)b * Tc + c * CHL) * Cc + h * Dc;
    for (int i = tid; i < 64 * 32; i += 256) {
        const int r = i >> 5, c4 = i & 31;
        const float w = exp2f(l2d * (float)r);
        float4 kv = *(const float4*)(g_k + base + (size_t)r * Cc + c4 * 4);
        kv.x *= w; kv.y *= w; kv.z *= w; kv.w *= w;
        *(float4*)&Ks[r][c4 * 4] = kv;
        *(float4*)&Vs[r][c4 * 4] = *(const float4*)(g_v + base + (size_t)r * Cc + c4 * 4);
    }
    __syncthreads();

    const int tx = tid & 15, ty = tid >> 4;
    float acc[8][8];
#pragma unroll
    for (int i = 0; i < 8; i++)
#pragma unroll
        for (int j = 0; j < 8; j++) acc[i][j] = 0.f;

#pragma unroll 4
    for (int j = 0; j < 64; j++) {
        float a[8], bb[8];
        *(float4*)(a)      = *(const float4*)&Ks[j][ty * 8];
        *(float4*)(a + 4)  = *(const float4*)&Ks[j][ty * 8 + 4];
        *(float4*)(bb)     = *(const float4*)&Vs[j][tx * 8];
        *(float4*)(bb + 4) = *(const float4*)&Vs[j][tx * 8 + 4];
#pragma unroll
        for (int i = 0; i < 8; i++)
#pragma unroll
            for (int jj = 0; jj < 8; jj++) acc[i][jj] += a[i] * bb[jj];
    }

    float* dst = g_stA + ((size_t)(b * Hc + h) * NCH + c) * (Dc * Dc);
#pragma unroll
    for (int i = 0; i < 8; i++) {
        float4 o0, o1;
        o0.x = acc[i][0]; o0.y = acc[i][1]; o0.z = acc[i][2]; o0.w = acc[i][3];
        o1.x = acc[i][4]; o1.y = acc[i][5]; o1.z = acc[i][6]; o1.w = acc[i][7];
        *(float4*)(dst + (size_t)(ty * 8 + i) * Dc + tx * 8)     = o0;
        *(float4*)(dst + (size_t)(ty * 8 + i) * Dc + tx * 8 + 4) = o1;
    }
}

// ---------------------------------------------------------------------------
// Phase B: backward scan (fp32)
// ---------------------------------------------------------------------------
__global__ void __launch_bounds__(256) k_scan(const float* __restrict__ dlog)
{
    const int bh = blockIdx.x;
    const int h = bh & (Hc - 1);
    const int tid = threadIdx.x;
    const float dec = 1.f / (1.f + expf(-dlog[h]));
    const float dL = exp2f(log2f(dec) * (float)CHL);

    float4 run[16];
#pragma unroll
    for (int r = 0; r < 16; r++) run[r] = make_float4(0.f, 0.f, 0.f, 0.f);

    for (int c = NCH - 1; c >= 1; c--) {
        const float4* A = (const float4*)(g_stA + ((size_t)bh * NCH + c) * (Dc * Dc));
        float4* Tt = (float4*)(g_stT + ((size_t)bh * NCH + (c - 1)) * (Dc * Dc));
#pragma unroll
        for (int r = 0; r < 16; r++) {
            float4 a = A[r * 256 + tid];
            run[r].x = a.x + dL * run[r].x;
            run[r].y = a.y + dL * run[r].y;
            run[r].z = a.z + dL * run[r].z;
            run[r].w = a.w + dL * run[r].w;
            Tt[r * 256 + tid] = run[r];
        }
    }
}

// ---------------------------------------------------------------------------
// Phase C: chunk attention (fp32)
// ---------------------------------------------------------------------------
#define SQP 132
#define SSP 80
#define CATTN_SMEM ((3 * 64 * SQP + 64 * SSP) * 4)

__global__ void __launch_bounds__(256) k_cattn(const float* __restrict__ dlog)
{
    extern __shared__ float sm[];
    float* Qs = sm;
    float* Ks = sm + 64 * SQP;
    float* Vs = sm + 2 * 64 * SQP;
    float* Ss = sm + 3 * 64 * SQP;

    const int c = blockIdx.x;
    const int h = blockIdx.y;
    const int b = blockIdx.z;
    const int tid = threadIdx.x;
    const int tg = tid >> 4;
    const int tc = tid & 15;

    const float dec = 1.f / (1.f + expf(-dlog[h]));
    const float l2d = log2f(dec);

    const size_t qbase = ((size_t)b * Tc + c * CHL) * Cc + h * Dc;

    for (int i = tid; i < 64 * 32; i += 256) {
        const int r = i >> 5, c4 = i & 31;
        *(float4*)(Qs + r * SQP + c4 * 4) =
            *(const float4*)(g_q + qbase + (size_t)r * Cc + c4 * 4);
        *(float4*)(Ks + r * SQP + c4 * 4) =
            *(const float4*)(g_k + qbase + (size_t)r * Cc + c4 * 4);
        *(float4*)(Vs + r * SQP + c4 * 4) =
            *(const float4*)(g_v + qbase + (size_t)r * Cc + c4 * 4);
    }
    __syncthreads();

    float acc[4][4];
#pragma unroll
    for (int i = 0; i < 4; i++)
#pragma unroll
        for (int j = 0; j < 4; j++) acc[i][j] = 0.f;

#pragma unroll 4
    for (int kk4 = 0; kk4 < 32; kk4++) {
        float4 qv[4], kv[4];
#pragma unroll
        for (int i = 0; i < 4; i++)
            qv[i] = *(const float4*)(Qs + (tg + 16 * i) * SQP + kk4 * 4);
#pragma unroll
        for (int j = 0; j < 4; j++)
            kv[j] = *(const float4*)(Ks + (tc + 16 * j) * SQP + kk4 * 4);
#pragma unroll
        for (int i = 0; i < 4; i++)
#pragma unroll
            for (int j = 0; j < 4; j++)
                acc[i][j] += qv[i].x * kv[j].x + qv[i].y * kv[j].y +
                             qv[i].z * kv[j].z + qv[i].w * kv[j].w;
    }

#pragma unroll
    for (int i = 0; i < 4; i++) {
        const int il = tg + 16 * i;
#pragma unroll
        for (int j = 0; j < 4; j++) {
            const int jl = tc + 16 * j;
            float wgt = 0.f;
            if (jl > il) wgt = exp2f(l2d * (float)(jl - il - 1));
            Ss[il * SSP + jl] = acc[i][j] * wgt;
        }
    }
    __syncthreads();

    float o[4][8];
#pragma unroll
    for (int i = 0; i < 4; i++)
#pragma unroll
        for (int j = 0; j < 8; j++) o[i][j] = 0.f;

#pragma unroll 4
    for (int j = 0; j < 64; j++) {
        const float s0 = Ss[(tg)      * SSP + j];
        const float s1 = Ss[(tg + 16) * SSP + j];
        const float s2 = Ss[(tg + 32) * SSP + j];
        const float s3 = Ss[(tg + 48) * SSP + j];
        const float4 v0 = *(const float4*)(Vs + j * SQP + tc * 8);
        const float4 v1 = *(const float4*)(Vs + j * SQP + tc * 8 + 4);
        o[0][0] += s0 * v0.x; o[0][1] += s0 * v0.y; o[0][2] += s0 * v0.z; o[0][3] += s0 * v0.w;
        o[0][4] += s0 * v1.x; o[0][5] += s0 * v1.y; o[0][6] += s0 * v1.z; o[0][7] += s0 * v1.w;
        o[1][0] += s1 * v0.x; o[1][1] += s1 * v0.y; o[1][2] += s1 * v0.z; o[1][3] += s1 * v0.w;
        o[1][4] += s1 * v1.x; o[1][5] += s1 * v1.y; o[1][6] += s1 * v1.z; o[1][7] += s1 * v1.w;
        o[2][0] += s2 * v0.x; o[2][1] += s2 * v0.y; o[2][2] += s2 * v0.z; o[2][3] += s2 * v0.w;
        o[2][4] += s2 * v1.x; o[2][5] += s2 * v1.y; o[2][6] += s2 * v1.z; o[2][7] += s2 * v1.w;
        o[3][0] += s3 * v0.x; o[3][1] += s3 * v0.y; o[3][2] += s3 * v0.z; o[3][3] += s3 * v0.w;
        o[3][4] += s3 * v1.x; o[3][5] += s3 * v1.y; o[3][6] += s3 * v1.z; o[3][7] += s3 * v1.w;
    }

    if (c < NCH - 1) {
        float f[4];
#pragma unroll
        for (int i = 0; i < 4; i++)
            f[i] = exp2f(l2d * (float)(63 - (tg + 16 * i)));

        const float* Tsrc = g_stT + ((size_t)(b * Hc + h) * NCH + c) * (Dc * Dc);
        for (int d0 = 0; d0 < 128; d0 += 32) {
            __syncthreads();
            for (int i = tid; i < 32 * 32; i += 256) {
                const int r = i >> 5, c4 = i & 31;
                *(float4*)(Ks + r * SQP + c4 * 4) =
                    *(const float4*)(Tsrc + (size_t)(d0 + r) * Dc + c4 * 4);
            }
            __syncthreads();
#pragma unroll 8
            for (int dd = 0; dd < 32; dd++) {
                const float q0 = Qs[(tg)      * SQP + d0 + dd] * f[0];
                const float q1 = Qs[(tg + 16) * SQP + d0 + dd] * f[1];
                const float q2 = Qs[(tg + 32) * SQP + d0 + dd] * f[2];
                const float q3 = Qs[(tg + 48) * SQP + d0 + dd] * f[3];
                const float4 t0 = *(const float4*)(Ks + dd * SQP + tc * 8);
                const float4 t1 = *(const float4*)(Ks + dd * SQP + tc * 8 + 4);
                o[0][0] += q0 * t0.x; o[0][1] += q0 * t0.y; o[0][2] += q0 * t0.z; o[0][3] += q0 * t0.w;
                o[0][4] += q0 * t1.x; o[0][5] += q0 * t1.y; o[0][6] += q0 * t1.z; o[0][7] += q0 * t1.w;
                o[1][0] += q1 * t0.x; o[1][1] += q1 * t0.y; o[1][2] += q1 * t0.z; o[1][3] += q1 * t0.w;
                o[1][4] += q1 * t1.x; o[1][5] += q1 * t1.y; o[1][6] += q1 * t1.z; o[1][7] += q1 * t1.w;
                o[2][0] += q2 * t0.x; o[2][1] += q2 * t0.y; o[2][2] += q2 * t0.z; o[2][3] += q2 * t0.w;
                o[2][4] += q2 * t1.x; o[2][5] += q2 * t1.y; o[2][6] += q2 * t1.z; o[2][7] += q2 * t1.w;
                o[3][0] += q3 * t0.x; o[3][1] += q3 * t0.y; o[3][2] += q3 * t0.z; o[3][3] += q3 * t0.w;
                o[3][4] += q3 * t1.x; o[3][5] += q3 * t1.y; o[3][6] += q3 * t1.z; o[3][7] += q3 * t1.w;
            }
        }
    }

#pragma unroll
    for (int i = 0; i < 4; i++) {
        float4 o0, o1;
        o0.x = o[i][0]; o0.y = o[i][1]; o0.z = o[i][2]; o0.w = o[i][3];
        o1.x = o[i][4]; o1.y = o[i][5]; o1.z = o[i][6]; o1.w = o[i][7];
        float* dst = g_r + qbase + (size_t)(tg + 16 * i) * Cc + tc * 8;
        *(float4*)(dst)     = o0;
        *(float4*)(dst + 4) = o1;
    }
}

extern "C" void kernel_launch(void* const* d_in, const int* in_sizes, int n_in,
                              void* d_out, int out_size)
{
    const float* x     = (const float*)d_in[0];
    const float* basis = (const float*)d_in[1];
    const float* wq    = (const float*)d_in[2];
    const float* wk    = (const float*)d_in[3];
    const float* vc    = (const float*)d_in[4];
    const float* oc    = (const float*)d_in[5];
    const float* dlog  = (const float*)d_in[6];
    const float* oscal = (const float*)d_in[7];
    float* out = (float*)d_out;

    (void)in_sizes; (void)n_in; (void)out_size;

    cudaFuncSetAttribute(k_state, cudaFuncAttributeMaxDynamicSharedMemorySize,
                         STATE_SMEM);
    cudaFuncSetAttribute(k_cattn, cudaFuncAttributeMaxDynamicSharedMemorySize,
                         CATTN_SMEM);
    cudaFuncSetAttribute(k_gemm_proj, cudaFuncAttributeMaxDynamicSharedMemorySize,
                         GS_BYTES);
    cudaFuncSetAttribute(k_gemm_out, cudaFuncAttributeMaxDynamicSharedMemorySize,
                         GS_BYTES);

    // Weight prep + splits
    k_weights<<<dim3(Cc / 128, Vc / 128, 2), 256>>>(basis, vc, oc);
    k_split<<<(MROWS * Cc / 4 + 255) / 256, 256>>>(x, 0, MROWS * Cc / 4);
    k_splitT<<<dim3(16, 16, 3), dim3(32, 32)>>>(wq, wk);
    k_split<<<(Vc * Cc / 4 + 255) / 256, 256>>>(nullptr, 1, Vc * Cc / 4);

    // Projections on tensor cores (warp mma)
    k_gemm_proj<<<dim3(Cc / 128, MROWS / 128, 3), 256, GS_BYTES>>>();
    k_norm<<<MROWS, 256>>>();

    // Chunked linear attention (fp32)
    k_state<<<dim3(NCH - 1, Hc, Bc), 256, STATE_SMEM>>>(dlog);
    k_scan<<<16, 256>>>(dlog);
    k_cattn<<<dim3(NCH, Hc, Bc), 256, CATTN_SMEM>>>(dlog);

    // Output projection on tensor cores (warp mma)
    k_split<<<(MROWS * Cc / 4 + 255) / 256, 256>>>(nullptr, 2, MROWS * Cc / 4);
    k_gemm_out<<<dim3(Vc / 128, MROWS / 128), 256, GS_BYTES>>>(out, oscal);
}

// round 5
// speedup vs baseline: 3.6334x; 1.4984x over previous
#include <cuda_runtime.h>
#include <cuda_bf16.h>
#include <cstdint>

// Problem constants (fixed by the dataset)
#define Bc 4
#define Tc 2048
#define Vc 512
#define Cc 512
#define Hc 4
#define Dc 128
#define NBc 128
#define MROWS (Bc*Tc)    // 8192
#define NCH 32
#define CHL 64

// fp32 scratch
__device__ float g_vw[Vc*Cc];
__device__ float g_ow[Vc*Cc];
__device__ float g_q[MROWS*Cc];
__device__ float g_k[MROWS*Cc];
__device__ float g_v[MROWS*Cc];
__device__ float g_stA[(size_t)16*NCH*Dc*Dc];
__device__ float g_stT[(size_t)16*NCH*Dc*Dc];

// bf16 split scratch
__device__ __nv_bfloat16 g_xh[MROWS*Cc],  g_xl[MROWS*Cc];
__device__ __nv_bfloat16 g_rh[MROWS*Cc],  g_rl[MROWS*Cc];
__device__ __nv_bfloat16 g_qnh[MROWS*Cc], g_qnl[MROWS*Cc];
__device__ __nv_bfloat16 g_knh[MROWS*Cc], g_knl[MROWS*Cc];
__device__ __nv_bfloat16 g_vsh[MROWS*Cc], g_vsl[MROWS*Cc];
__device__ __nv_bfloat16 g_wqTh[Cc*Vc],   g_wqTl[Cc*Vc];
__device__ __nv_bfloat16 g_wkTh[Cc*Vc],   g_wkTl[Cc*Vc];
__device__ __nv_bfloat16 g_vwTh[Cc*Vc],   g_vwTl[Cc*Vc];
__device__ __nv_bfloat16 g_owh[Vc*Cc],    g_owl[Vc*Cc];
// T^T splits: [bh][c][e][d]
__device__ __nv_bfloat16 g_sTh[(size_t)16*NCH*Dc*Dc];
__device__ __nv_bfloat16 g_sTl[(size_t)16*NCH*Dc*Dc];

// ===========================================================================
// Helpers
// ===========================================================================
__device__ __forceinline__ uint32_t smem_u32(const void* p) {
    uint32_t a;
    asm("{ .reg .u64 t; cvta.to.shared.u64 t, %1; cvt.u32.u64 %0, t; }"
        : "=r"(a) : "l"(p));
    return a;
}
__device__ __forceinline__ void ldm_x4(uint32_t* r, uint32_t addr) {
    asm volatile("ldmatrix.sync.aligned.m8n8.x4.shared.b16 {%0,%1,%2,%3}, [%4];"
                 : "=r"(r[0]), "=r"(r[1]), "=r"(r[2]), "=r"(r[3]) : "r"(addr));
}
__device__ __forceinline__ void mma_bf16(float* c, const uint32_t* a,
                                         const uint32_t* b) {
    asm volatile(
        "mma.sync.aligned.m16n8k16.row.col.f32.bf16.bf16.f32 "
        "{%0,%1,%2,%3}, {%4,%5,%6,%7}, {%8,%9}, {%0,%1,%2,%3};"
        : "+f"(c[0]), "+f"(c[1]), "+f"(c[2]), "+f"(c[3])
        : "r"(a[0]), "r"(a[1]), "r"(a[2]), "r"(a[3]), "r"(b[0]), "r"(b[1]));
}
__device__ __forceinline__ void cp16(uint32_t dst, const void* src) {
    asm volatile("cp.async.cg.shared.global [%0], [%1], 16;"
                 :: "r"(dst), "l"(src));
}
__device__ __forceinline__ void cp_commit() {
    asm volatile("cp.async.commit_group;");
}
template <int N>
__device__ __forceinline__ void cp_wait() {
    asm volatile("cp.async.wait_group %0;" :: "n"(N));
}
__device__ __forceinline__ void split2(float v, __nv_bfloat16& h,
                                       __nv_bfloat16& l) {
    h = __float2bfloat16_rn(v);
    l = __float2bfloat16_rn(v - __bfloat162float(h));
}

// ===========================================================================
// Double-buffered split-bf16 warp-MMA GEMM: C[128,128] = A[M,512]@B[N,512]^T
// ===========================================================================
#define GSLAB 18432                 // 128 rows * 144B
#define GBUF  (4 * GSLAB)           // 73728
#define GS_BYTES (2 * GBUF)         // 147456

__device__ __forceinline__ void gemm_mma_tile(
    const __nv_bfloat16* __restrict__ Ah, const __nv_bfloat16* __restrict__ Al,
    const __nv_bfloat16* __restrict__ Bh, const __nv_bfloat16* __restrict__ Bl,
    float* __restrict__ Cp, float alpha, int tm, int tn)
{
    extern __shared__ __align__(16) char smc[];
    const int tid = threadIdx.x, lane = tid & 31, wid = tid >> 5;
    const int wm = wid >> 2, wn = wid & 3;
    const uint32_t sb = smem_u32(smc);

    float acc[4][4][4];
#pragma unroll
    for (int i = 0; i < 4; i++)
#pragma unroll
        for (int j = 0; j < 4; j++)
#pragma unroll
            for (int q = 0; q < 4; q++) acc[i][j][q] = 0.f;

    const int crow = tid >> 3, cq = tid & 7;
    const __nv_bfloat16* bases[4];
    bases[0] = Ah + ((size_t)tm * 128) * 512;
    bases[1] = Al + ((size_t)tm * 128) * 512;
    bases[2] = Bh + ((size_t)tn * 128) * 512;
    bases[3] = Bl + ((size_t)tn * 128) * 512;

    auto issue = [&](int c, int buf) {
        const uint32_t bb = sb + buf * GBUF;
#pragma unroll
        for (int s = 0; s < 4; s++) {
            const __nv_bfloat16* src = bases[s] + c * 64;
#pragma unroll
            for (int i = 0; i < 4; i++) {
                const int row = crow + 32 * i;
                cp16(bb + s * GSLAB + row * 144 + cq * 16,
                     src + (size_t)row * 512 + cq * 8);
            }
        }
        cp_commit();
    };

    issue(0, 0);
    issue(1, 1);

    const uint32_t a_lrow = wm * 64 + (lane & 15);
    const uint32_t a_koff = (lane >> 4) * 8;
    const uint32_t b_lrow = wn * 32 + (lane & 7) + ((lane >> 4) << 3);
    const uint32_t b_koff = ((lane >> 3) & 1) * 8;

    for (int c = 0; c < 8; c++) {
        if (c == 7) cp_wait<0>(); else cp_wait<1>();
        __syncthreads();
        const uint32_t bb = sb + (c & 1) * GBUF;

#pragma unroll
        for (int ks = 0; ks < 4; ks++) {
            const int k0 = ks * 16;
            uint32_t bh[8], bl[8];
#pragma unroll
            for (int nf = 0; nf < 2; nf++) {
                const uint32_t boff =
                    (b_lrow + nf * 16) * 144 + (k0 + b_koff) * 2;
                ldm_x4(bh + nf * 4, bb + 2 * GSLAB + boff);
                ldm_x4(bl + nf * 4, bb + 3 * GSLAB + boff);
            }
#pragma unroll
            for (int mi = 0; mi < 4; mi++) {
                uint32_t a[4];
                const uint32_t aoff =
                    (a_lrow + mi * 16) * 144 + (k0 + a_koff) * 2;
                ldm_x4(a, bb + 0 * GSLAB + aoff);
#pragma unroll
                for (int ni = 0; ni < 4; ni++) {
                    mma_bf16(acc[mi][ni], a, bh + ni * 2);
                    mma_bf16(acc[mi][ni], a, bl + ni * 2);
                }
            }
#pragma unroll
            for (int mi = 0; mi < 4; mi++) {
                uint32_t a[4];
                const uint32_t aoff =
                    (a_lrow + mi * 16) * 144 + (k0 + a_koff) * 2;
                ldm_x4(a, bb + 1 * GSLAB + aoff);
#pragma unroll
                for (int ni = 0; ni < 4; ni++)
                    mma_bf16(acc[mi][ni], a, bh + ni * 2);
            }
        }
        __syncthreads();
        if (c + 2 < 8) issue(c + 2, c & 1);
    }

    const int qr = lane >> 2, qc = lane & 3;
#pragma unroll
    for (int mi = 0; mi < 4; mi++) {
#pragma unroll
        for (int ni = 0; ni < 4; ni++) {
            const int m = tm * 128 + wm * 64 + mi * 16 + qr;
            const int n = tn * 128 + wn * 32 + ni * 8 + qc * 2;
            float2 v0, v1;
            v0.x = acc[mi][ni][0] * alpha; v0.y = acc[mi][ni][1] * alpha;
            v1.x = acc[mi][ni][2] * alpha; v1.y = acc[mi][ni][3] * alpha;
            *(float2*)(Cp + (size_t)m * 512 + n)       = v0;
            *(float2*)(Cp + (size_t)(m + 8) * 512 + n) = v1;
        }
    }
}

__global__ void __launch_bounds__(256) k_gemm_proj()
{
    const __nv_bfloat16 *Bh, *Bl; float* Cp;
    if (blockIdx.z == 0)      { Bh = g_wqTh; Bl = g_wqTl; Cp = g_q; }
    else if (blockIdx.z == 1) { Bh = g_wkTh; Bl = g_wkTl; Cp = g_k; }
    else                      { Bh = g_vwTh; Bl = g_vwTl; Cp = g_v; }
    gemm_mma_tile(g_xh, g_xl, Bh, Bl, Cp, 1.f, blockIdx.y, blockIdx.x);
}

__global__ void __launch_bounds__(256) k_gemm_out(float* __restrict__ out,
                                                  const float* __restrict__ os)
{
    gemm_mma_tile(g_rh, g_rl, g_owh, g_owl, out, __ldg(os), blockIdx.y,
                  blockIdx.x);
}

// ===========================================================================
// Split kernels
// mode 0: x -> xh/xl ; mode 1: g_ow -> owh/owl ; mode 2: g_v -> vsh/vsl
// ===========================================================================
__global__ void __launch_bounds__(256) k_split(const float* __restrict__ xin,
                                               int mode, int n4)
{
    const float* in = (mode == 0) ? xin : (mode == 1 ? g_ow : g_v);
    __nv_bfloat16* oh = (mode == 0) ? g_xh : (mode == 1 ? g_owh : g_vsh);
    __nv_bfloat16* ol = (mode == 0) ? g_xl : (mode == 1 ? g_owl : g_vsl);
    int i = blockIdx.x * 256 + threadIdx.x;
    if (i >= n4) return;
    float4 v = ((const float4*)in)[i];
    __nv_bfloat16 h0, h1, h2, h3, l0, l1, l2, l3;
    split2(v.x, h0, l0); split2(v.y, h1, l1);
    split2(v.z, h2, l2); split2(v.w, h3, l3);
    __nv_bfloat162 ph0; ph0.x = h0; ph0.y = h1;
    __nv_bfloat162 ph1; ph1.x = h2; ph1.y = h3;
    __nv_bfloat162 pl0; pl0.x = l0; pl0.y = l1;
    __nv_bfloat162 pl1; pl1.x = l2; pl1.y = l3;
    ((__nv_bfloat162*)oh)[2 * i]     = ph0;
    ((__nv_bfloat162*)oh)[2 * i + 1] = ph1;
    ((__nv_bfloat162*)ol)[2 * i]     = pl0;
    ((__nv_bfloat162*)ol)[2 * i + 1] = pl1;
}

// Transpose + split 512x512 weights
__global__ void __launch_bounds__(1024) k_splitT(const float* __restrict__ wq,
                                                 const float* __restrict__ wk)
{
    __shared__ float t[32][33];
    const float* in = (blockIdx.z == 0) ? wq : (blockIdx.z == 1 ? wk : g_vw);
    __nv_bfloat16* oh = (blockIdx.z == 0) ? g_wqTh : (blockIdx.z == 1 ? g_wkTh : g_vwTh);
    __nv_bfloat16* ol = (blockIdx.z == 0) ? g_wqTl : (blockIdx.z == 1 ? g_wkTl : g_vwTl);
    const int x = blockIdx.x * 32 + threadIdx.x;
    const int y = blockIdx.y * 32 + threadIdx.y;
    t[threadIdx.y][threadIdx.x] = in[y * 512 + x];
    __syncthreads();
    const float v = t[threadIdx.x][threadIdx.y];
    const int ox = blockIdx.y * 32 + threadIdx.x;
    const int oy = blockIdx.x * 32 + threadIdx.y;
    __nv_bfloat16 h, l;
    split2(v, h, l);
    oh[oy * 512 + ox] = h;
    ol[oy * 512 + ox] = l;
}

// Transpose + split chunk states T: [d][e] fp32 -> [e][d] bf16 hi/lo
__global__ void __launch_bounds__(1024) k_tsplit()
{
    __shared__ float t[32][33];
    const int z = blockIdx.z;
    const int bh = z / (NCH - 1), c = z % (NCH - 1);
    const float* in = g_stT + ((size_t)bh * NCH + c) * (Dc * Dc);
    __nv_bfloat16* oh = g_sTh + ((size_t)bh * NCH + c) * (Dc * Dc);
    __nv_bfloat16* ol = g_sTl + ((size_t)bh * NCH + c) * (Dc * Dc);
    const int x = blockIdx.x * 32 + threadIdx.x;   // e
    const int y = blockIdx.y * 32 + threadIdx.y;   // d
    t[threadIdx.y][threadIdx.x] = in[y * 128 + x];
    __syncthreads();
    const float v = t[threadIdx.x][threadIdx.y];
    const int ox = blockIdx.y * 32 + threadIdx.x;  // d
    const int oy = blockIdx.x * 32 + threadIdx.y;  // e
    __nv_bfloat16 h, l;
    split2(v, h, l);
    oh[oy * 128 + ox] = h;
    ol[oy * 128 + ox] = l;
}

// ===========================================================================
// fp32 GEMM (tiny k_weights only)
// ===========================================================================
__global__ void __launch_bounds__(256) k_weights(
    const float* __restrict__ basis, const float* __restrict__ vc,
    const float* __restrict__ oc)
{
    __shared__ float As[8][132];
    __shared__ float Bs[8][132];
    const float* B = (blockIdx.z == 0) ? vc : oc;
    float* C = (blockIdx.z == 0) ? g_vw : g_ow;
    const int bx = blockIdx.x, by = blockIdx.y;
    const int tid = threadIdx.x;
    const int tx = tid & 15, ty = tid >> 4;

    float acc[8][8];
#pragma unroll
    for (int i = 0; i < 8; i++)
#pragma unroll
        for (int j = 0; j < 8; j++) acc[i][j] = 0.f;

    const float* Ab = basis + (size_t)(by * 128) * NBc;

    for (int k0 = 0; k0 < NBc; k0 += 8) {
        {
            const int ar = tid >> 1, ac = (tid & 1) * 4;
            float4 v = *(const float4*)(Ab + (size_t)ar * NBc + k0 + ac);
            As[ac + 0][ar] = v.x; As[ac + 1][ar] = v.y;
            As[ac + 2][ar] = v.z; As[ac + 3][ar] = v.w;
        }
        {
            const int br = tid >> 1, bc = (tid & 1) * 4;
            float4 v = *(const float4*)(B + (size_t)(bx * 128 + br) * NBc + k0 + bc);
            Bs[bc + 0][br] = v.x; Bs[bc + 1][br] = v.y;
            Bs[bc + 2][br] = v.z; Bs[bc + 3][br] = v.w;
        }
        __syncthreads();

#pragma unroll
        for (int kk = 0; kk < 8; kk++) {
            float a[8], bf[8];
            *(float4*)(a)     = *(const float4*)&As[kk][ty * 8];
            *(float4*)(a + 4) = *(const float4*)&As[kk][ty * 8 + 4];
            *(float4*)(bf)     = *(const float4*)&Bs[kk][tx * 8];
            *(float4*)(bf + 4) = *(const float4*)&Bs[kk][tx * 8 + 4];
#pragma unroll
            for (int i = 0; i < 8; i++)
#pragma unroll
                for (int j = 0; j < 8; j++) acc[i][j] += a[i] * bf[j];
        }
        __syncthreads();
    }

    float* Cb = C + (size_t)(by * 128 + ty * 8) * Cc + bx * 128 + tx * 8;
#pragma unroll
    for (int i = 0; i < 8; i++) {
        float4 o0, o1;
        o0.x = acc[i][0]; o0.y = acc[i][1]; o0.z = acc[i][2]; o0.w = acc[i][3];
        o1.x = acc[i][4]; o1.y = acc[i][5]; o1.z = acc[i][6]; o1.w = acc[i][7];
        *(float4*)(Cb + (size_t)i * Cc)     = o0;
        *(float4*)(Cb + (size_t)i * Cc + 4) = o1;
    }
}

// L2-normalize rows of g_q/g_k, write bf16 splits
__global__ void __launch_bounds__(256) k_norm()
{
    const int row = blockIdx.x;
    const float* q = g_q + (size_t)row * Cc;
    const float* k = g_k + (size_t)row * Cc;
    const int t = threadIdx.x;
    float q0 = q[t], q1 = q[t + 256];
    float k0 = k[t], k1 = k[t + 256];
    float sq = q0 * q0 + q1 * q1;
    float sk = k0 * k0 + k1 * k1;
#pragma unroll
    for (int off = 16; off; off >>= 1) {
        sq += __shfl_xor_sync(0xffffffffu, sq, off);
        sk += __shfl_xor_sync(0xffffffffu, sk, off);
    }
    __shared__ float rq[8], rk[8];
    __shared__ float inv[2];
    const int w = t >> 5, l = t & 31;
    if (l == 0) { rq[w] = sq; rk[w] = sk; }
    __syncthreads();
    if (t == 0) {
        float a = 0.f, cc = 0.f;
#pragma unroll
        for (int i = 0; i < 8; i++) { a += rq[i]; cc += rk[i]; }
        inv[0] = 1.f / fmaxf(sqrtf(a), 1e-12f);
        inv[1] = 1.f / fmaxf(sqrtf(cc), 1e-12f);
    }
    __syncthreads();
    const float iq = inv[0], ik = inv[1];
    __nv_bfloat16 h, lo;
    const size_t b = (size_t)row * Cc;
    split2(q0 * iq, h, lo); g_qnh[b + t] = h;       g_qnl[b + t] = lo;
    split2(q1 * iq, h, lo); g_qnh[b + t + 256] = h; g_qnl[b + t + 256] = lo;
    split2(k0 * ik, h, lo); g_knh[b + t] = h;       g_knl[b + t] = lo;
    split2(k1 * ik, h, lo); g_knh[b + t + 256] = h; g_knl[b + t + 256] = lo;
}

// ===========================================================================
// Phase A (MMA): A_c = (diag(d^j) K)^T V  per (b,h,c)
// smem: KT_H/KT_L/VT_H/VT_L each [128 d][64 j] bf16 pitch 144B
// ===========================================================================
#define ST_KH 0
#define ST_KL 18432
#define ST_VH 36864
#define ST_VL 55296
#define STATE_SMEM 73728

__global__ void __launch_bounds__(256) k_state(const float* __restrict__ dlog)
{
    extern __shared__ __align__(16) char sm[];
    const int c = blockIdx.x + 1, h = blockIdx.y, b = blockIdx.z;
    const int tid = threadIdx.x, lane = tid & 31, wid = tid >> 5;
    const float dec = 1.f / (1.f + expf(-dlog[h]));
    const float l2d = log2f(dec);
    const size_t gb = ((size_t)b * Tc + c * CHL) * Cc + h * Dc;

#pragma unroll
    for (int i = 0; i < 32; i++) {
        const int idx = tid + 256 * i;
        const int d = idx & 127, j = idx >> 7;
        const float kv = __bfloat162float(g_knh[gb + (size_t)j * Cc + d]) +
                         __bfloat162float(g_knl[gb + (size_t)j * Cc + d]);
        const float s = kv * exp2f(l2d * (float)j);
        __nv_bfloat16 hh, ll;
        split2(s, hh, ll);
        *(__nv_bfloat16*)(sm + ST_KH + d * 144 + j * 2) = hh;
        *(__nv_bfloat16*)(sm + ST_KL + d * 144 + j * 2) = ll;
        *(__nv_bfloat16*)(sm + ST_VH + d * 144 + j * 2) =
            g_vsh[gb + (size_t)j * Cc + d];
        *(__nv_bfloat16*)(sm + ST_VL + d * 144 + j * 2) =
            g_vsl[gb + (size_t)j * Cc + d];
    }
    __syncthreads();

    const int wm = wid >> 2, wn = wid & 3;
    const uint32_t sb = smem_u32(sm);
    const uint32_t a_lrow = wm * 64 + (lane & 15);
    const uint32_t a_koff = (lane >> 4) * 8;
    const uint32_t b_lrow = wn * 32 + (lane & 7) + ((lane >> 4) << 3);
    const uint32_t b_koff = ((lane >> 3) & 1) * 8;

    float acc[4][4][4];
#pragma unroll
    for (int i = 0; i < 4; i++)
#pragma unroll
        for (int j = 0; j < 4; j++)
#pragma unroll
            for (int q = 0; q < 4; q++) acc[i][j][q] = 0.f;

#pragma unroll
    for (int ks = 0; ks < 4; ks++) {
        const int k0 = ks * 16;
        uint32_t vh[8], vl[8];
#pragma unroll
        for (int nf = 0; nf < 2; nf++) {
            const uint32_t boff = (b_lrow + nf * 16) * 144 + (k0 + b_koff) * 2;
            ldm_x4(vh + nf * 4, sb + ST_VH + boff);
            ldm_x4(vl + nf * 4, sb + ST_VL + boff);
        }
#pragma unroll
        for (int mi = 0; mi < 4; mi++) {
            uint32_t ah[4], al[4];
            const uint32_t aoff = (a_lrow + mi * 16) * 144 + (k0 + a_koff) * 2;
            ldm_x4(ah, sb + ST_KH + aoff);
            ldm_x4(al, sb + ST_KL + aoff);
#pragma unroll
            for (int ni = 0; ni < 4; ni++) {
                mma_bf16(acc[mi][ni], ah, vh + ni * 2);
                mma_bf16(acc[mi][ni], al, vh + ni * 2);
                mma_bf16(acc[mi][ni], ah, vl + ni * 2);
            }
        }
    }

    float* dst = g_stA + ((size_t)(b * Hc + h) * NCH + c) * (Dc * Dc);
    const int qr = lane >> 2, qc = lane & 3;
#pragma unroll
    for (int mi = 0; mi < 4; mi++) {
#pragma unroll
        for (int ni = 0; ni < 4; ni++) {
            const int m = wm * 64 + mi * 16 + qr;
            const int n = wn * 32 + ni * 8 + qc * 2;
            float2 v0, v1;
            v0.x = acc[mi][ni][0]; v0.y = acc[mi][ni][1];
            v1.x = acc[mi][ni][2]; v1.y = acc[mi][ni][3];
            *(float2*)(dst + (size_t)m * Dc + n)       = v0;
            *(float2*)(dst + (size_t)(m + 8) * Dc + n) = v1;
        }
    }
}

// ===========================================================================
// Phase B: backward scan, elementwise over state -> parallel grid (16,16)
// ===========================================================================
__global__ void __launch_bounds__(256) k_scan(const float* __restrict__ dlog)
{
    const int bh = blockIdx.x;
    const int h = bh & (Hc - 1);
    const int idx4 = blockIdx.y * 256 + threadIdx.x;   // float4 index 0..4095
    const float dec = 1.f / (1.f + expf(-dlog[h]));
    const float dL = exp2f(log2f(dec) * (float)CHL);

    float4 run = make_float4(0.f, 0.f, 0.f, 0.f);
    for (int c = NCH - 2; c >= 0; c--) {
        const float4* A =
            (const float4*)(g_stA + ((size_t)bh * NCH + c + 1) * (Dc * Dc));
        float4* Tt = (float4*)(g_stT + ((size_t)bh * NCH + c) * (Dc * Dc));
        float4 a = A[idx4];
        run.x = a.x + dL * run.x;
        run.y = a.y + dL * run.y;
        run.z = a.z + dL * run.z;
        run.w = a.w + dL * run.w;
        Tt[idx4] = run;
    }
}

// ===========================================================================
// Phase C (MMA): intra masked attention + inter Q@T^T, split precision.
// ===========================================================================
#define CQ_H 0
#define CQ_L 17408
#define CK_H 34816        // K tile (64x272B) / T slabs (128x144B)
#define CK_L 53248
#define CV_H 71680        // V^T [128 d][64 j] pitch 144B
#define CV_L 90112
#define CS_H 108544       // S [64 i][64 j] pitch 144B
#define CS_L 117760
#define CATTN_SMEM 126976

__global__ void __launch_bounds__(256) k_cattn(const float* __restrict__ dlog)
{
    extern __shared__ __align__(16) char sm[];
    const int c = blockIdx.x, h = blockIdx.y, b = blockIdx.z;
    const int tid = threadIdx.x, lane = tid & 31, wid = tid >> 5;
    const int wm = wid >> 2, wn = wid & 3;
    const float dec = 1.f / (1.f + expf(-dlog[h]));
    const float l2d = log2f(dec);
    const size_t gb = ((size_t)b * Tc + c * CHL) * Cc + h * Dc;
    const uint32_t sb = smem_u32(sm);

    // Straight loads: Q,K hi/lo tiles 64x128, pitch 272B
    {
        const uint4* s0 = (const uint4*)(g_qnh + gb);
        const uint4* s1 = (const uint4*)(g_qnl + gb);
        const uint4* s2 = (const uint4*)(g_knh + gb);
        const uint4* s3 = (const uint4*)(g_knl + gb);
#pragma unroll
        for (int i = 0; i < 4; i++) {
            const int idx = tid + 256 * i;
            const int row = idx >> 4, q = idx & 15;
            const size_t so = (size_t)row * 64 + q;
            const uint32_t doff = row * 272 + q * 16;
            *(uint4*)(sm + CQ_H + doff) = s0[so];
            *(uint4*)(sm + CQ_L + doff) = s1[so];
            *(uint4*)(sm + CK_H + doff) = s2[so];
            *(uint4*)(sm + CK_L + doff) = s3[so];
        }
    }
    // Transposed V loads: VT[d][j]
#pragma unroll
    for (int i = 0; i < 32; i++) {
        const int idx = tid + 256 * i;
        const int d = idx & 127, j = idx >> 7;
        *(__nv_bfloat16*)(sm + CV_H + d * 144 + j * 2) =
            g_vsh[gb + (size_t)j * Cc + d];
        *(__nv_bfloat16*)(sm + CV_L + d * 144 + j * 2) =
            g_vsl[gb + (size_t)j * Cc + d];
    }
    __syncthreads();

    const uint32_t a_koff = (lane >> 4) * 8;
    const uint32_t b_koff = ((lane >> 3) & 1) * 8;
    const uint32_t aQ_row = wm * 32 + (lane & 15);      // Q/S A rows
    const uint32_t bS_row = wn * 16 + (lane & 7) + ((lane >> 4) << 3);
    const uint32_t bO_row = wn * 32 + (lane & 7) + ((lane >> 4) << 3);
    const int qr = lane >> 2, qc = lane & 3;

    // ---- intra: S = Q K^T (64x64), warp tile 32x16 ----
    float accS[2][2][4];
#pragma unroll
    for (int i = 0; i < 2; i++)
#pragma unroll
        for (int j = 0; j < 2; j++)
#pragma unroll
            for (int q = 0; q < 4; q++) accS[i][j][q] = 0.f;

#pragma unroll
    for (int ks = 0; ks < 8; ks++) {
        const int k0 = ks * 16;
        uint32_t kh[4], kl[4];
        const uint32_t boff = bS_row * 272 + (k0 + b_koff) * 2;
        ldm_x4(kh, sb + CK_H + boff);
        ldm_x4(kl, sb + CK_L + boff);
#pragma unroll
        for (int mi = 0; mi < 2; mi++) {
            uint32_t qh[4], ql[4];
            const uint32_t aoff = (aQ_row + mi * 16) * 272 + (k0 + a_koff) * 2;
            ldm_x4(qh, sb + CQ_H + aoff);
            ldm_x4(ql, sb + CQ_L + aoff);
#pragma unroll
            for (int ni = 0; ni < 2; ni++) {
                mma_bf16(accS[mi][ni], qh, kh + ni * 2);
                mma_bf16(accS[mi][ni], ql, kh + ni * 2);
                mma_bf16(accS[mi][ni], qh, kl + ni * 2);
            }
        }
    }

    // mask + split-store S
#pragma unroll
    for (int mi = 0; mi < 2; mi++) {
#pragma unroll
        for (int ni = 0; ni < 2; ni++) {
#pragma unroll
            for (int q = 0; q < 4; q++) {
                const int il = wm * 32 + mi * 16 + qr + (q >> 1) * 8;
                const int jl = wn * 16 + ni * 8 + qc * 2 + (q & 1);
                float s = 0.f;
                if (jl > il)
                    s = accS[mi][ni][q] * exp2f(l2d * (float)(jl - il - 1));
                __nv_bfloat16 hh, ll;
                split2(s, hh, ll);
                *(__nv_bfloat16*)(sm + CS_H + il * 144 + jl * 2) = hh;
                *(__nv_bfloat16*)(sm + CS_L + il * 144 + jl * 2) = ll;
            }
        }
    }
    __syncthreads();

    // ---- O accumulators: warp tile 32x32 over 64x128 ----
    float acc[2][4][4], accI[2][4][4];
#pragma unroll
    for (int i = 0; i < 2; i++)
#pragma unroll
        for (int j = 0; j < 4; j++)
#pragma unroll
            for (int q = 0; q < 4; q++) { acc[i][j][q] = 0.f; accI[i][j][q] = 0.f; }

    // intra SV: K=64
#pragma unroll
    for (int ks = 0; ks < 4; ks++) {
        const int k0 = ks * 16;
        uint32_t vh[8], vl[8];
#pragma unroll
        for (int nf = 0; nf < 2; nf++) {
            const uint32_t boff = (bO_row + nf * 16) * 144 + (k0 + b_koff) * 2;
            ldm_x4(vh + nf * 4, sb + CV_H + boff);
            ldm_x4(vl + nf * 4, sb + CV_L + boff);
        }
#pragma unroll
        for (int mi = 0; mi < 2; mi++) {
            uint32_t sh[4], sl[4];
            const uint32_t aoff = (aQ_row + mi * 16) * 144 + (k0 + a_koff) * 2;
            ldm_x4(sh, sb + CS_H + aoff);
            ldm_x4(sl, sb + CS_L + aoff);
#pragma unroll
            for (int ni = 0; ni < 4; ni++) {
                mma_bf16(acc[mi][ni], sh, vh + ni * 2);
                mma_bf16(acc[mi][ni], sl, vh + ni * 2);
                mma_bf16(acc[mi][ni], sh, vl + ni * 2);
            }
        }
    }

    // inter: O_i += Q @ T^T, T slabs streamed through CK buffers
    if (c < NCH - 1) {
        const __nv_bfloat16* Th =
            g_sTh + ((size_t)(b * Hc + h) * NCH + c) * (Dc * Dc);
        const __nv_bfloat16* Tl =
            g_sTl + ((size_t)(b * Hc + h) * NCH + c) * (Dc * Dc);
#pragma unroll
        for (int slab = 0; slab < 2; slab++) {
            __syncthreads();
#pragma unroll
            for (int i = 0; i < 4; i++) {
                const int idx = tid + 256 * i;
                const int e = idx >> 3, q8 = idx & 7;
                *(uint4*)(sm + CK_H + e * 144 + q8 * 16) =
                    *(const uint4*)(Th + (size_t)e * 128 + slab * 64 + q8 * 8);
                *(uint4*)(sm + CK_L + e * 144 + q8 * 16) =
                    *(const uint4*)(Tl + (size_t)e * 128 + slab * 64 + q8 * 8);
            }
            __syncthreads();
#pragma unroll
            for (int ks = 0; ks < 4; ks++) {
                const int k0 = ks * 16;
                uint32_t th[8], tl[8];
#pragma unroll
                for (int nf = 0; nf < 2; nf++) {
                    const uint32_t boff =
                        (bO_row + nf * 16) * 144 + (k0 + b_koff) * 2;
                    ldm_x4(th + nf * 4, sb + CK_H + boff);
                    ldm_x4(tl + nf * 4, sb + CK_L + boff);
                }
#pragma unroll
                for (int mi = 0; mi < 2; mi++) {
                    uint32_t qh[4], ql[4];
                    const uint32_t aoff = (aQ_row + mi * 16) * 272 +
                                          (slab * 64 + k0 + a_koff) * 2;
                    ldm_x4(qh, sb + CQ_H + aoff);
                    ldm_x4(ql, sb + CQ_L + aoff);
#pragma unroll
                    for (int ni = 0; ni < 4; ni++) {
                        mma_bf16(accI[mi][ni], qh, th + ni * 2);
                        mma_bf16(accI[mi][ni], ql, th + ni * 2);
                        mma_bf16(accI[mi][ni], qh, tl + ni * 2);
                    }
                }
            }
        }
    }

    // epilogue: O = acc + f(row) * accI, split-write to g_rh/g_rl
#pragma unroll
    for (int mi = 0; mi < 2; mi++) {
        const int r0 = wm * 32 + mi * 16 + qr;
        const float f0 = exp2f(l2d * (float)(63 - r0));
        const float f1 = exp2f(l2d * (float)(63 - (r0 + 8)));
#pragma unroll
        for (int ni = 0; ni < 4; ni++) {
            const int col = wn * 32 + ni * 8 + qc * 2;
            const size_t a0 = gb + (size_t)r0 * Cc + col;
            const size_t a1 = gb + (size_t)(r0 + 8) * Cc + col;
            float o0 = acc[mi][ni][0] + f0 * accI[mi][ni][0];
            float o1 = acc[mi][ni][1] + f0 * accI[mi][ni][1];
            float o2 = acc[mi][ni][2] + f1 * accI[mi][ni][2];
            float o3 = acc[mi][ni][3] + f1 * accI[mi][ni][3];
            __nv_bfloat16 h0, l0, h1, l1, h2, l2, h3, l3;
            split2(o0, h0, l0); split2(o1, h1, l1);
            split2(o2, h2, l2); split2(o3, h3, l3);
            __nv_bfloat162 p;
            p.x = h0; p.y = h1; *(__nv_bfloat162*)(g_rh + a0) = p;
            p.x = l0; p.y = l1; *(__nv_bfloat162*)(g_rl + a0) = p;
            p.x = h2; p.y = h3; *(__nv_bfloat162*)(g_rh + a1) = p;
            p.x = l2; p.y = l3; *(__nv_bfloat162*)(g_rl + a1) = p;
        }
    }
}

extern "C" void kernel_launch(void* const* d_in, const int* in_sizes, int n_in,
                              void* d_out, int out_size)
{
    const float* x     = (const float*)d_in[0];
    const float* basis = (const float*)d_in[1];
    const float* wq    = (const float*)d_in[2];
    const float* wk    = (const float*)d_in[3];
    const float* vc    = (const float*)d_in[4];
    const float* oc    = (const float*)d_in[5];
    const float* dlog  = (const float*)d_in[6];
    const float* oscal = (const float*)d_in[7];
    float* out = (float*)d_out;

    (void)in_sizes; (void)n_in; (void)out_size;

    cudaFuncSetAttribute(k_state, cudaFuncAttributeMaxDynamicSharedMemorySize,
                         STATE_SMEM);
    cudaFuncSetAttribute(k_cattn, cudaFuncAttributeMaxDynamicSharedMemorySize,
                         CATTN_SMEM);
    cudaFuncSetAttribute(k_gemm_proj, cudaFuncAttributeMaxDynamicSharedMemorySize,
                         GS_BYTES);
    cudaFuncSetAttribute(k_gemm_out, cudaFuncAttributeMaxDynamicSharedMemorySize,
                         GS_BYTES);

    // Weight prep + splits
    k_weights<<<dim3(Cc / 128, Vc / 128, 2), 256>>>(basis, vc, oc);
    k_split<<<(MROWS * Cc / 4 + 255) / 256, 256>>>(x, 0, MROWS * Cc / 4);
    k_splitT<<<dim3(16, 16, 3), dim3(32, 32)>>>(wq, wk);
    k_split<<<(Vc * Cc / 4 + 255) / 256, 256>>>(nullptr, 1, Vc * Cc / 4);

    // Projections (tensor cores, double-buffered)
    k_gemm_proj<<<dim3(Cc / 128, MROWS / 128, 3), 256, GS_BYTES>>>();
    k_norm<<<MROWS, 256>>>();
    k_split<<<(MROWS * Cc / 4 + 255) / 256, 256>>>(nullptr, 2, MROWS * Cc / 4);

    // Chunked linear attention (tensor cores)
    k_state<<<dim3(NCH - 1, Hc, Bc), 256, STATE_SMEM>>>(dlog);
    k_scan<<<dim3(16, 16), 256>>>(dlog);
    k_tsplit<<<dim3(4, 4, 16 * (NCH - 1)), dim3(32, 32)>>>();
    k_cattn<<<dim3(NCH, Hc, Bc), 256, CATTN_SMEM>>>(dlog);

    // Output projection
    k_gemm_out<<<dim3(Vc / 128, MROWS / 128), 256, GS_BYTES>>>(out, oscal);
}

// round 6
// speedup vs baseline: 3.9450x; 1.0858x over previous
#include <cuda_runtime.h>
#include <cuda_bf16.h>
#include <cstdint>

// Problem constants
#define Bc 4
#define Tc 2048
#define Vc 512
#define Cc 512
#define Hc 4
#define Dc 128
#define NBc 128
#define MROWS (Bc*Tc)    // 8192
#define NCH 32
#define CHL 64

// fp32 scratch
__device__ float g_q[MROWS*Cc];
__device__ float g_k[MROWS*Cc];
__device__ float g_stA[(size_t)16*NCH*Dc*Dc];   // holds A^T per chunk

// bf16 split scratch
__device__ __nv_bfloat16 g_xh[MROWS*Cc],  g_xl[MROWS*Cc];
__device__ __nv_bfloat16 g_rh[MROWS*Cc],  g_rl[MROWS*Cc];
__device__ __nv_bfloat16 g_qnh[MROWS*Cc], g_qnl[MROWS*Cc];
__device__ __nv_bfloat16 g_knh[MROWS*Cc], g_knl[MROWS*Cc];
__device__ __nv_bfloat16 g_vsh[MROWS*Cc], g_vsl[MROWS*Cc];
__device__ __nv_bfloat16 g_wqTh[Cc*Vc],   g_wqTl[Cc*Vc];
__device__ __nv_bfloat16 g_wkTh[Cc*Vc],   g_wkTl[Cc*Vc];
__device__ __nv_bfloat16 g_vwTh[Cc*Vc],   g_vwTl[Cc*Vc];
__device__ __nv_bfloat16 g_owh[Vc*Cc],    g_owl[Vc*Cc];
// T^T splits: [bh][c][e][d]
__device__ __nv_bfloat16 g_sTh[(size_t)16*NCH*Dc*Dc];
__device__ __nv_bfloat16 g_sTl[(size_t)16*NCH*Dc*Dc];

// ===========================================================================
// Helpers
// ===========================================================================
__device__ __forceinline__ uint32_t smem_u32(const void* p) {
    uint32_t a;
    asm("{ .reg .u64 t; cvta.to.shared.u64 t, %1; cvt.u32.u64 %0, t; }"
        : "=r"(a) : "l"(p));
    return a;
}
__device__ __forceinline__ void ldm_x4(uint32_t* r, uint32_t addr) {
    asm volatile("ldmatrix.sync.aligned.m8n8.x4.shared.b16 {%0,%1,%2,%3}, [%4];"
                 : "=r"(r[0]), "=r"(r[1]), "=r"(r[2]), "=r"(r[3]) : "r"(addr));
}
__device__ __forceinline__ void mma_bf16(float* c, const uint32_t* a,
                                         const uint32_t* b) {
    asm volatile(
        "mma.sync.aligned.m16n8k16.row.col.f32.bf16.bf16.f32 "
        "{%0,%1,%2,%3}, {%4,%5,%6,%7}, {%8,%9}, {%0,%1,%2,%3};"
        : "+f"(c[0]), "+f"(c[1]), "+f"(c[2]), "+f"(c[3])
        : "r"(a[0]), "r"(a[1]), "r"(a[2]), "r"(a[3]), "r"(b[0]), "r"(b[1]));
}
__device__ __forceinline__ void cp16(uint32_t dst, const void* src) {
    asm volatile("cp.async.cg.shared.global [%0], [%1], 16;"
                 :: "r"(dst), "l"(src));
}
__device__ __forceinline__ void cp_commit() {
    asm volatile("cp.async.commit_group;");
}
template <int N>
__device__ __forceinline__ void cp_wait() {
    asm volatile("cp.async.wait_group %0;" :: "n"(N));
}
__device__ __forceinline__ void split2(float v, __nv_bfloat16& h,
                                       __nv_bfloat16& l) {
    h = __float2bfloat16_rn(v);
    l = __float2bfloat16_rn(v - __bfloat162float(h));
}

// ===========================================================================
// Double-buffered split-bf16 warp-MMA GEMM (K-slab 32, 2 CTAs/SM).
// C[128,128] = A[M,512]@B[N,512]^T. Output fp32 (Cp) or bf16 splits (Oh/Ol).
// ===========================================================================
#define GSLAB 10240                 // 128 rows * 80B
#define GBUF  (4 * GSLAB)           // 40960
#define GS_BYTES (2 * GBUF)         // 81920

__device__ __forceinline__ void gemm_mma_tile(
    const __nv_bfloat16* __restrict__ Ah, const __nv_bfloat16* __restrict__ Al,
    const __nv_bfloat16* __restrict__ Bh, const __nv_bfloat16* __restrict__ Bl,
    float* __restrict__ Cp, __nv_bfloat16* __restrict__ Oh,
    __nv_bfloat16* __restrict__ Ol, float alpha, int tm, int tn)
{
    extern __shared__ __align__(16) char smc[];
    const int tid = threadIdx.x, lane = tid & 31, wid = tid >> 5;
    const int wm = wid >> 2, wn = wid & 3;
    const uint32_t sb = smem_u32(smc);

    float acc[4][4][4];
#pragma unroll
    for (int i = 0; i < 4; i++)
#pragma unroll
        for (int j = 0; j < 4; j++)
#pragma unroll
            for (int q = 0; q < 4; q++) acc[i][j][q] = 0.f;

    const __nv_bfloat16* bases[4];
    bases[0] = Ah + ((size_t)tm * 128) * 512;
    bases[1] = Al + ((size_t)tm * 128) * 512;
    bases[2] = Bh + ((size_t)tn * 128) * 512;
    bases[3] = Bl + ((size_t)tn * 128) * 512;

    auto issue = [&](int c, int buf) {
        const uint32_t bb = sb + buf * GBUF;
#pragma unroll
        for (int s = 0; s < 4; s++) {
            const __nv_bfloat16* src = bases[s] + c * 32;
#pragma unroll
            for (int i = 0; i < 2; i++) {
                const int idx = tid + 256 * i;
                const int row = idx >> 2, q = idx & 3;
                cp16(bb + s * GSLAB + row * 80 + q * 16,
                     src + (size_t)row * 512 + q * 8);
            }
        }
        cp_commit();
    };

    issue(0, 0);
    issue(1, 1);

    const uint32_t a_lrow = wm * 64 + (lane & 15);
    const uint32_t a_koff = (lane >> 4) * 8;
    const uint32_t b_lrow = wn * 32 + (lane & 7) + ((lane >> 4) << 3);
    const uint32_t b_koff = ((lane >> 3) & 1) * 8;

    for (int c = 0; c < 16; c++) {
        if (c == 15) cp_wait<0>(); else cp_wait<1>();
        __syncthreads();
        const uint32_t bb = sb + (c & 1) * GBUF;

#pragma unroll
        for (int ks = 0; ks < 2; ks++) {
            const int k0 = ks * 16;
            uint32_t bh[8], bl[8];
#pragma unroll
            for (int nf = 0; nf < 2; nf++) {
                const uint32_t boff =
                    (b_lrow + nf * 16) * 80 + (k0 + b_koff) * 2;
                ldm_x4(bh + nf * 4, bb + 2 * GSLAB + boff);
                ldm_x4(bl + nf * 4, bb + 3 * GSLAB + boff);
            }
#pragma unroll
            for (int mi = 0; mi < 4; mi++) {
                uint32_t a[4];
                const uint32_t aoff =
                    (a_lrow + mi * 16) * 80 + (k0 + a_koff) * 2;
                ldm_x4(a, bb + 0 * GSLAB + aoff);
#pragma unroll
                for (int ni = 0; ni < 4; ni++) {
                    mma_bf16(acc[mi][ni], a, bh + ni * 2);
                    mma_bf16(acc[mi][ni], a, bl + ni * 2);
                }
            }
#pragma unroll
            for (int mi = 0; mi < 4; mi++) {
                uint32_t a[4];
                const uint32_t aoff =
                    (a_lrow + mi * 16) * 80 + (k0 + a_koff) * 2;
                ldm_x4(a, bb + 1 * GSLAB + aoff);
#pragma unroll
                for (int ni = 0; ni < 4; ni++)
                    mma_bf16(acc[mi][ni], a, bh + ni * 2);
            }
        }
        __syncthreads();
        if (c + 2 < 16) issue(c + 2, c & 1);
    }

    const int qr = lane >> 2, qc = lane & 3;
#pragma unroll
    for (int mi = 0; mi < 4; mi++) {
#pragma unroll
        for (int ni = 0; ni < 4; ni++) {
            const int m = tm * 128 + wm * 64 + mi * 16 + qr;
            const int n = tn * 128 + wn * 32 + ni * 8 + qc * 2;
            float o0 = acc[mi][ni][0] * alpha, o1 = acc[mi][ni][1] * alpha;
            float o2 = acc[mi][ni][2] * alpha, o3 = acc[mi][ni][3] * alpha;
            if (Cp) {
                float2 v0, v1;
                v0.x = o0; v0.y = o1; v1.x = o2; v1.y = o3;
                *(float2*)(Cp + (size_t)m * 512 + n)       = v0;
                *(float2*)(Cp + (size_t)(m + 8) * 512 + n) = v1;
            } else {
                __nv_bfloat16 h0, l0, h1, l1, h2, l2, h3, l3;
                split2(o0, h0, l0); split2(o1, h1, l1);
                split2(o2, h2, l2); split2(o3, h3, l3);
                __nv_bfloat162 p;
                p.x = h0; p.y = h1;
                *(__nv_bfloat162*)(Oh + (size_t)m * 512 + n) = p;
                p.x = l0; p.y = l1;
                *(__nv_bfloat162*)(Ol + (size_t)m * 512 + n) = p;
                p.x = h2; p.y = h3;
                *(__nv_bfloat162*)(Oh + (size_t)(m + 8) * 512 + n) = p;
                p.x = l2; p.y = l3;
                *(__nv_bfloat162*)(Ol + (size_t)(m + 8) * 512 + n) = p;
            }
        }
    }
}

__global__ void __launch_bounds__(256) k_gemm_proj()
{
    if (blockIdx.z == 0)
        gemm_mma_tile(g_xh, g_xl, g_wqTh, g_wqTl, g_q, nullptr, nullptr, 1.f,
                      blockIdx.y, blockIdx.x);
    else if (blockIdx.z == 1)
        gemm_mma_tile(g_xh, g_xl, g_wkTh, g_wkTl, g_k, nullptr, nullptr, 1.f,
                      blockIdx.y, blockIdx.x);
    else
        gemm_mma_tile(g_xh, g_xl, g_vwTh, g_vwTl, nullptr, g_vsh, g_vsl, 1.f,
                      blockIdx.y, blockIdx.x);
}

__global__ void __launch_bounds__(256) k_gemm_out(float* __restrict__ out,
                                                  const float* __restrict__ os)
{
    gemm_mma_tile(g_rh, g_rl, g_owh, g_owl, out, nullptr, nullptr, __ldg(os),
                  blockIdx.y, blockIdx.x);
}

// ===========================================================================
// Split x
// ===========================================================================
__global__ void __launch_bounds__(256) k_split(const float* __restrict__ in)
{
    int i = blockIdx.x * 256 + threadIdx.x;
    float4 v = ((const float4*)in)[i];
    __nv_bfloat16 h0, h1, h2, h3, l0, l1, l2, l3;
    split2(v.x, h0, l0); split2(v.y, h1, l1);
    split2(v.z, h2, l2); split2(v.w, h3, l3);
    __nv_bfloat162 p;
    p.x = h0; p.y = h1; ((__nv_bfloat162*)g_xh)[2 * i]     = p;
    p.x = h2; p.y = h3; ((__nv_bfloat162*)g_xh)[2 * i + 1] = p;
    p.x = l0; p.y = l1; ((__nv_bfloat162*)g_xl)[2 * i]     = p;
    p.x = l2; p.y = l3; ((__nv_bfloat162*)g_xl)[2 * i + 1] = p;
}

// Transpose + split 512x512 weights (wq, wk)
__global__ void __launch_bounds__(1024) k_splitT(const float* __restrict__ wq,
                                                 const float* __restrict__ wk)
{
    __shared__ float t[32][33];
    const float* in = (blockIdx.z == 0) ? wq : wk;
    __nv_bfloat16* oh = (blockIdx.z == 0) ? g_wqTh : g_wkTh;
    __nv_bfloat16* ol = (blockIdx.z == 0) ? g_wqTl : g_wkTl;
    const int x = blockIdx.x * 32 + threadIdx.x;
    const int y = blockIdx.y * 32 + threadIdx.y;
    t[threadIdx.y][threadIdx.x] = in[y * 512 + x];
    __syncthreads();
    const float v = t[threadIdx.x][threadIdx.y];
    const int ox = blockIdx.y * 32 + threadIdx.x;
    const int oy = blockIdx.x * 32 + threadIdx.y;
    __nv_bfloat16 h, l;
    split2(v, h, l);
    oh[oy * 512 + ox] = h;
    ol[oy * 512 + ox] = l;
}

// ===========================================================================
// k_weights: z=0: vwT[c][v] = vc @ basis^T ; z=1: ow[v][c] = basis @ oc^T
// fp32 compute, bf16-split epilogue. M=N=512, K=128 (NT).
// ===========================================================================
__global__ void __launch_bounds__(256) k_weights(
    const float* __restrict__ basis, const float* __restrict__ vc,
    const float* __restrict__ oc)
{
    __shared__ float As[8][132];
    __shared__ float Bs[8][132];
    const int z = blockIdx.z;
    const float* A = z ? basis : vc;
    const float* B = z ? oc : basis;
    __nv_bfloat16* Oh = z ? g_owh : g_vwTh;
    __nv_bfloat16* Ol = z ? g_owl : g_vwTl;
    const int bx = blockIdx.x, by = blockIdx.y;
    const int tid = threadIdx.x;
    const int tx = tid & 15, ty = tid >> 4;

    float acc[8][8];
#pragma unroll
    for (int i = 0; i < 8; i++)
#pragma unroll
        for (int j = 0; j < 8; j++) acc[i][j] = 0.f;

    const float* Ab = A + (size_t)(by * 128) * NBc;

    for (int k0 = 0; k0 < NBc; k0 += 8) {
        {
            const int ar = tid >> 1, ac = (tid & 1) * 4;
            float4 v = *(const float4*)(Ab + (size_t)ar * NBc + k0 + ac);
            As[ac + 0][ar] = v.x; As[ac + 1][ar] = v.y;
            As[ac + 2][ar] = v.z; As[ac + 3][ar] = v.w;
        }
        {
            const int br = tid >> 1, bc = (tid & 1) * 4;
            float4 v = *(const float4*)(B + (size_t)(bx * 128 + br) * NBc + k0 + bc);
            Bs[bc + 0][br] = v.x; Bs[bc + 1][br] = v.y;
            Bs[bc + 2][br] = v.z; Bs[bc + 3][br] = v.w;
        }
        __syncthreads();

#pragma unroll
        for (int kk = 0; kk < 8; kk++) {
            float a[8], bf[8];
            *(float4*)(a)     = *(const float4*)&As[kk][ty * 8];
            *(float4*)(a + 4) = *(const float4*)&As[kk][ty * 8 + 4];
            *(float4*)(bf)     = *(const float4*)&Bs[kk][tx * 8];
            *(float4*)(bf + 4) = *(const float4*)&Bs[kk][tx * 8 + 4];
#pragma unroll
            for (int i = 0; i < 8; i++)
#pragma unroll
                for (int j = 0; j < 8; j++) acc[i][j] += a[i] * bf[j];
        }
        __syncthreads();
    }

#pragma unroll
    for (int i = 0; i < 8; i++) {
        const size_t rowb = (size_t)(by * 128 + ty * 8 + i) * 512 + bx * 128 + tx * 8;
#pragma unroll
        for (int j = 0; j < 8; j += 2) {
            __nv_bfloat16 h0, l0, h1, l1;
            split2(acc[i][j], h0, l0);
            split2(acc[i][j + 1], h1, l1);
            __nv_bfloat162 p;
            p.x = h0; p.y = h1; *(__nv_bfloat162*)(Oh + rowb + j) = p;
            p.x = l0; p.y = l1; *(__nv_bfloat162*)(Ol + rowb + j) = p;
        }
    }
}

// L2-normalize rows of g_q/g_k, write bf16 splits
__global__ void __launch_bounds__(256) k_norm()
{
    const int row = blockIdx.x;
    const float* q = g_q + (size_t)row * Cc;
    const float* k = g_k + (size_t)row * Cc;
    const int t = threadIdx.x;
    float q0 = q[t], q1 = q[t + 256];
    float k0 = k[t], k1 = k[t + 256];
    float sq = q0 * q0 + q1 * q1;
    float sk = k0 * k0 + k1 * k1;
#pragma unroll
    for (int off = 16; off; off >>= 1) {
        sq += __shfl_xor_sync(0xffffffffu, sq, off);
        sk += __shfl_xor_sync(0xffffffffu, sk, off);
    }
    __shared__ float rq[8], rk[8];
    __shared__ float inv[2];
    const int w = t >> 5, l = t & 31;
    if (l == 0) { rq[w] = sq; rk[w] = sk; }
    __syncthreads();
    if (t == 0) {
        float a = 0.f, cc = 0.f;
#pragma unroll
        for (int i = 0; i < 8; i++) { a += rq[i]; cc += rk[i]; }
        inv[0] = 1.f / fmaxf(sqrtf(a), 1e-12f);
        inv[1] = 1.f / fmaxf(sqrtf(cc), 1e-12f);
    }
    __syncthreads();
    const float iq = inv[0], ik = inv[1];
    __nv_bfloat16 h, lo;
    const size_t b = (size_t)row * Cc;
    split2(q0 * iq, h, lo); g_qnh[b + t] = h;       g_qnl[b + t] = lo;
    split2(q1 * iq, h, lo); g_qnh[b + t + 256] = h; g_qnl[b + t + 256] = lo;
    split2(k0 * ik, h, lo); g_knh[b + t] = h;       g_knl[b + t] = lo;
    split2(k1 * ik, h, lo); g_knh[b + t + 256] = h; g_knl[b + t + 256] = lo;
}

// ===========================================================================
// Phase A (MMA): A^T_c[e][d] = sum_j V[j][e] * (d^j K[j][d]) per (b,h,c)
// A-operand = V^T slabs, B-operand = decayed K^T slabs.
// ===========================================================================
#define ST_KH 0
#define ST_KL 18432
#define ST_VH 36864
#define ST_VL 55296
#define STATE_SMEM 73728

__global__ void __launch_bounds__(256) k_state(const float* __restrict__ dlog)
{
    extern __shared__ __align__(16) char sm[];
    const int c = blockIdx.x + 1, h = blockIdx.y, b = blockIdx.z;
    const int tid = threadIdx.x, lane = tid & 31, wid = tid >> 5;
    const float dec = 1.f / (1.f + expf(-dlog[h]));
    const float l2d = log2f(dec);
    const size_t gb = ((size_t)b * Tc + c * CHL) * Cc + h * Dc;

#pragma unroll
    for (int i = 0; i < 32; i++) {
        const int idx = tid + 256 * i;
        const int d = idx & 127, j = idx >> 7;
        const float kv = __bfloat162float(g_knh[gb + (size_t)j * Cc + d]) +
                         __bfloat162float(g_knl[gb + (size_t)j * Cc + d]);
        const float s = kv * exp2f(l2d * (float)j);
        __nv_bfloat16 hh, ll;
        split2(s, hh, ll);
        *(__nv_bfloat16*)(sm + ST_KH + d * 144 + j * 2) = hh;
        *(__nv_bfloat16*)(sm + ST_KL + d * 144 + j * 2) = ll;
        *(__nv_bfloat16*)(sm + ST_VH + d * 144 + j * 2) =
            g_vsh[gb + (size_t)j * Cc + d];
        *(__nv_bfloat16*)(sm + ST_VL + d * 144 + j * 2) =
            g_vsl[gb + (size_t)j * Cc + d];
    }
    __syncthreads();

    const int wm = wid >> 2, wn = wid & 3;
    const uint32_t sb = smem_u32(sm);
    const uint32_t a_lrow = wm * 64 + (lane & 15);
    const uint32_t a_koff = (lane >> 4) * 8;
    const uint32_t b_lrow = wn * 32 + (lane & 7) + ((lane >> 4) << 3);
    const uint32_t b_koff = ((lane >> 3) & 1) * 8;

    float acc[4][4][4];
#pragma unroll
    for (int i = 0; i < 4; i++)
#pragma unroll
        for (int j = 0; j < 4; j++)
#pragma unroll
            for (int q = 0; q < 4; q++) acc[i][j][q] = 0.f;

#pragma unroll
    for (int ks = 0; ks < 4; ks++) {
        const int k0 = ks * 16;
        uint32_t kh[8], kl[8];
#pragma unroll
        for (int nf = 0; nf < 2; nf++) {
            const uint32_t boff = (b_lrow + nf * 16) * 144 + (k0 + b_koff) * 2;
            ldm_x4(kh + nf * 4, sb + ST_KH + boff);
            ldm_x4(kl + nf * 4, sb + ST_KL + boff);
        }
#pragma unroll
        for (int mi = 0; mi < 4; mi++) {
            uint32_t vh[4], vl[4];
            const uint32_t aoff = (a_lrow + mi * 16) * 144 + (k0 + a_koff) * 2;
            ldm_x4(vh, sb + ST_VH + aoff);
            ldm_x4(vl, sb + ST_VL + aoff);
#pragma unroll
            for (int ni = 0; ni < 4; ni++) {
                mma_bf16(acc[mi][ni], vh, kh + ni * 2);
                mma_bf16(acc[mi][ni], vl, kh + ni * 2);
                mma_bf16(acc[mi][ni], vh, kl + ni * 2);
            }
        }
    }

    float* dst = g_stA + ((size_t)(b * Hc + h) * NCH + c) * (Dc * Dc);
    const int qr = lane >> 2, qc = lane & 3;
#pragma unroll
    for (int mi = 0; mi < 4; mi++) {
#pragma unroll
        for (int ni = 0; ni < 4; ni++) {
            const int m = wm * 64 + mi * 16 + qr;
            const int n = wn * 32 + ni * 8 + qc * 2;
            float2 v0, v1;
            v0.x = acc[mi][ni][0]; v0.y = acc[mi][ni][1];
            v1.x = acc[mi][ni][2]; v1.y = acc[mi][ni][3];
            *(float2*)(dst + (size_t)m * Dc + n)       = v0;
            *(float2*)(dst + (size_t)(m + 8) * Dc + n) = v1;
        }
    }
}

// ===========================================================================
// Phase B: backward scan on A^T, writes split bf16 T^T directly.
// ===========================================================================
__global__ void __launch_bounds__(256) k_scan(const float* __restrict__ dlog)
{
    const int bh = blockIdx.x;
    const int h = bh & (Hc - 1);
    const int idx4 = blockIdx.y * 256 + threadIdx.x;   // 0..4095
    const float dec = 1.f / (1.f + expf(-dlog[h]));
    const float dL = exp2f(log2f(dec) * (float)CHL);

    float4 run = make_float4(0.f, 0.f, 0.f, 0.f);
    for (int c = NCH - 2; c >= 0; c--) {
        const float4* A =
            (const float4*)(g_stA + ((size_t)bh * NCH + c + 1) * (Dc * Dc));
        float4 a = A[idx4];
        run.x = a.x + dL * run.x;
        run.y = a.y + dL * run.y;
        run.z = a.z + dL * run.z;
        run.w = a.w + dL * run.w;
        const size_t o = ((size_t)bh * NCH + c) * (Dc * Dc) + (size_t)idx4 * 4;
        __nv_bfloat16 h0, l0, h1, l1, h2, l2, h3, l3;
        split2(run.x, h0, l0); split2(run.y, h1, l1);
        split2(run.z, h2, l2); split2(run.w, h3, l3);
        __nv_bfloat162 p;
        p.x = h0; p.y = h1; *(__nv_bfloat162*)(g_sTh + o)     = p;
        p.x = h2; p.y = h3; *(__nv_bfloat162*)(g_sTh + o + 2) = p;
        p.x = l0; p.y = l1; *(__nv_bfloat162*)(g_sTl + o)     = p;
        p.x = l2; p.y = l3; *(__nv_bfloat162*)(g_sTl + o + 2) = p;
    }
}

// ===========================================================================
// Phase C (MMA): intra masked attention + inter Q@T^T, T prefetched whole.
// ===========================================================================
#define CQ_H 0
#define CQ_L 17408
#define CK_H 34816
#define CK_L 52224
#define CV_H 69632
#define CV_L 88064
#define CS_H 106496
#define CS_L 115712
#define CT_H 124928
#define CT_L 159744
#define CATTN_SMEM 194560

__global__ void __launch_bounds__(256) k_cattn(const float* __restrict__ dlog)
{
    extern __shared__ __align__(16) char sm[];
    const int c = blockIdx.x, h = blockIdx.y, b = blockIdx.z;
    const int tid = threadIdx.x, lane = tid & 31, wid = tid >> 5;
    const int wm = wid >> 2, wn = wid & 3;
    const float dec = 1.f / (1.f + expf(-dlog[h]));
    const float l2d = log2f(dec);
    const size_t gb = ((size_t)b * Tc + c * CHL) * Cc + h * Dc;
    const uint32_t sb = smem_u32(sm);

    // Prefetch full T^T (both halves, hi+lo) with cp.async
    if (c < NCH - 1) {
        const __nv_bfloat16* Th =
            g_sTh + ((size_t)(b * Hc + h) * NCH + c) * (Dc * Dc);
        const __nv_bfloat16* Tl =
            g_sTl + ((size_t)(b * Hc + h) * NCH + c) * (Dc * Dc);
#pragma unroll
        for (int i = 0; i < 8; i++) {
            const int idx = tid + 256 * i;           // 0..2047
            const int e = idx >> 4, q = idx & 15;
            cp16(sb + CT_H + e * 272 + q * 16, Th + (size_t)e * 128 + q * 8);
            cp16(sb + CT_L + e * 272 + q * 16, Tl + (size_t)e * 128 + q * 8);
        }
    }
    cp_commit();

    // Q, K hi/lo tiles 64x128 pitch 272B
    {
        const uint4* s0 = (const uint4*)(g_qnh + gb);
        const uint4* s1 = (const uint4*)(g_qnl + gb);
        const uint4* s2 = (const uint4*)(g_knh + gb);
        const uint4* s3 = (const uint4*)(g_knl + gb);
#pragma unroll
        for (int i = 0; i < 4; i++) {
            const int idx = tid + 256 * i;
            const int row = idx >> 4, q = idx & 15;
            const size_t so = (size_t)row * 64 + q;
            const uint32_t doff = row * 272 + q * 16;
            *(uint4*)(sm + CQ_H + doff) = s0[so];
            *(uint4*)(sm + CQ_L + doff) = s1[so];
            *(uint4*)(sm + CK_H + doff) = s2[so];
            *(uint4*)(sm + CK_L + doff) = s3[so];
        }
    }
    // Transposed V: VT[d][j] pitch 144B
#pragma unroll
    for (int i = 0; i < 32; i++) {
        const int idx = tid + 256 * i;
        const int d = idx & 127, j = idx >> 7;
        *(__nv_bfloat16*)(sm + CV_H + d * 144 + j * 2) =
            g_vsh[gb + (size_t)j * Cc + d];
        *(__nv_bfloat16*)(sm + CV_L + d * 144 + j * 2) =
            g_vsl[gb + (size_t)j * Cc + d];
    }
    __syncthreads();

    const uint32_t a_koff = (lane >> 4) * 8;
    const uint32_t b_koff = ((lane >> 3) & 1) * 8;
    const uint32_t aQ_row = wm * 32 + (lane & 15);
    const uint32_t bS_row = wn * 16 + (lane & 7) + ((lane >> 4) << 3);
    const uint32_t bO_row = wn * 32 + (lane & 7) + ((lane >> 4) << 3);
    const int qr = lane >> 2, qc = lane & 3;

    // ---- intra: S = Q K^T ----
    float accS[2][2][4];
#pragma unroll
    for (int i = 0; i < 2; i++)
#pragma unroll
        for (int j = 0; j < 2; j++)
#pragma unroll
            for (int q = 0; q < 4; q++) accS[i][j][q] = 0.f;

#pragma unroll
    for (int ks = 0; ks < 8; ks++) {
        const int k0 = ks * 16;
        uint32_t kh[4], kl[4];
        const uint32_t boff = bS_row * 272 + (k0 + b_koff) * 2;
        ldm_x4(kh, sb + CK_H + boff);
        ldm_x4(kl, sb + CK_L + boff);
#pragma unroll
        for (int mi = 0; mi < 2; mi++) {
            uint32_t qh[4], ql[4];
            const uint32_t aoff = (aQ_row + mi * 16) * 272 + (k0 + a_koff) * 2;
            ldm_x4(qh, sb + CQ_H + aoff);
            ldm_x4(ql, sb + CQ_L + aoff);
#pragma unroll
            for (int ni = 0; ni < 2; ni++) {
                mma_bf16(accS[mi][ni], qh, kh + ni * 2);
                mma_bf16(accS[mi][ni], ql, kh + ni * 2);
                mma_bf16(accS[mi][ni], qh, kl + ni * 2);
            }
        }
    }

    // mask + split-store S
#pragma unroll
    for (int mi = 0; mi < 2; mi++) {
#pragma unroll
        for (int ni = 0; ni < 2; ni++) {
#pragma unroll
            for (int q = 0; q < 4; q++) {
                const int il = wm * 32 + mi * 16 + qr + (q >> 1) * 8;
                const int jl = wn * 16 + ni * 8 + qc * 2 + (q & 1);
                float s = 0.f;
                if (jl > il)
                    s = accS[mi][ni][q] * exp2f(l2d * (float)(jl - il - 1));
                __nv_bfloat16 hh, ll;
                split2(s, hh, ll);
                *(__nv_bfloat16*)(sm + CS_H + il * 144 + jl * 2) = hh;
                *(__nv_bfloat16*)(sm + CS_L + il * 144 + jl * 2) = ll;
            }
        }
    }
    cp_wait<0>();
    __syncthreads();

    // ---- O accumulators ----
    float acc[2][4][4], accI[2][4][4];
#pragma unroll
    for (int i = 0; i < 2; i++)
#pragma unroll
        for (int j = 0; j < 4; j++)
#pragma unroll
            for (int q = 0; q < 4; q++) { acc[i][j][q] = 0.f; accI[i][j][q] = 0.f; }

    // intra SV: K=64
#pragma unroll
    for (int ks = 0; ks < 4; ks++) {
        const int k0 = ks * 16;
        uint32_t vh[8], vl[8];
#pragma unroll
        for (int nf = 0; nf < 2; nf++) {
            const uint32_t boff = (bO_row + nf * 16) * 144 + (k0 + b_koff) * 2;
            ldm_x4(vh + nf * 4, sb + CV_H + boff);
            ldm_x4(vl + nf * 4, sb + CV_L + boff);
        }
#pragma unroll
        for (int mi = 0; mi < 2; mi++) {
            uint32_t sh[4], sl[4];
            const uint32_t aoff = (aQ_row + mi * 16) * 144 + (k0 + a_koff) * 2;
            ldm_x4(sh, sb + CS_H + aoff);
            ldm_x4(sl, sb + CS_L + aoff);
#pragma unroll
            for (int ni = 0; ni < 4; ni++) {
                mma_bf16(acc[mi][ni], sh, vh + ni * 2);
                mma_bf16(acc[mi][ni], sl, vh + ni * 2);
                mma_bf16(acc[mi][ni], sh, vl + ni * 2);
            }
        }
    }

    // inter: O_i += Q @ T^T, K=128, T resident in CT
    if (c < NCH - 1) {
#pragma unroll
        for (int ks = 0; ks < 8; ks++) {
            const int k0 = ks * 16;
            uint32_t th[8], tl[8];
#pragma unroll
            for (int nf = 0; nf < 2; nf++) {
                const uint32_t boff =
                    (bO_row + nf * 16) * 272 + (k0 + b_koff) * 2;
                ldm_x4(th + nf * 4, sb + CT_H + boff);
                ldm_x4(tl + nf * 4, sb + CT_L + boff);
            }
#pragma unroll
            for (int mi = 0; mi < 2; mi++) {
                uint32_t qh[4], ql[4];
                const uint32_t aoff =
                    (aQ_row + mi * 16) * 272 + (k0 + a_koff) * 2;
                ldm_x4(qh, sb + CQ_H + aoff);
                ldm_x4(ql, sb + CQ_L + aoff);
#pragma unroll
                for (int ni = 0; ni < 4; ni++) {
                    mma_bf16(accI[mi][ni], qh, th + ni * 2);
                    mma_bf16(accI[mi][ni], ql, th + ni * 2);
                    mma_bf16(accI[mi][ni], qh, tl + ni * 2);
                }
            }
        }
    }

    // epilogue: O = acc + f(row) * accI -> split write g_rh/g_rl
#pragma unroll
    for (int mi = 0; mi < 2; mi++) {
        const int r0 = wm * 32 + mi * 16 + qr;
        const float f0 = exp2f(l2d * (float)(63 - r0));
        const float f1 = exp2f(l2d * (float)(63 - (r0 + 8)));
#pragma unroll
        for (int ni = 0; ni < 4; ni++) {
            const int col = wn * 32 + ni * 8 + qc * 2;
            const size_t a0 = gb + (size_t)r0 * Cc + col;
            const size_t a1 = gb + (size_t)(r0 + 8) * Cc + col;
            float o0 = acc[mi][ni][0] + f0 * accI[mi][ni][0];
            float o1 = acc[mi][ni][1] + f0 * accI[mi][ni][1];
            float o2 = acc[mi][ni][2] + f1 * accI[mi][ni][2];
            float o3 = acc[mi][ni][3] + f1 * accI[mi][ni][3];
            __nv_bfloat16 h0, l0, h1, l1, h2, l2, h3, l3;
            split2(o0, h0, l0); split2(o1, h1, l1);
            split2(o2, h2, l2); split2(o3, h3, l3);
            __nv_bfloat162 p;
            p.x = h0; p.y = h1; *(__nv_bfloat162*)(g_rh + a0) = p;
            p.x = l0; p.y = l1; *(__nv_bfloat162*)(g_rl + a0) = p;
            p.x = h2; p.y = h3; *(__nv_bfloat162*)(g_rh + a1) = p;
            p.x = l2; p.y = l3; *(__nv_bfloat162*)(g_rl + a1) = p;
        }
    }
}

extern "C" void kernel_launch(void* const* d_in, const int* in_sizes, int n_in,
                              void* d_out, int out_size)
{
    const float* x     = (const float*)d_in[0];
    const float* basis = (const float*)d_in[1];
    const float* wq    = (const float*)d_in[2];
    const float* wk    = (const float*)d_in[3];
    const float* vc    = (const float*)d_in[4];
    const float* oc    = (const float*)d_in[5];
    const float* dlog  = (const float*)d_in[6];
    const float* oscal = (const float*)d_in[7];
    float* out = (float*)d_out;

    (void)in_sizes; (void)n_in; (void)out_size;

    cudaFuncSetAttribute(k_state, cudaFuncAttributeMaxDynamicSharedMemorySize,
                         STATE_SMEM);
    cudaFuncSetAttribute(k_cattn, cudaFuncAttributeMaxDynamicSharedMemorySize,
                         CATTN_SMEM);
    cudaFuncSetAttribute(k_gemm_proj, cudaFuncAttributeMaxDynamicSharedMemorySize,
                         GS_BYTES);
    cudaFuncSetAttribute(k_gemm_out, cudaFuncAttributeMaxDynamicSharedMemorySize,
                         GS_BYTES);

    k_weights<<<dim3(4, 4, 2), 256>>>(basis, vc, oc);
    k_split<<<MROWS * Cc / 4 / 256, 256>>>(x);
    k_splitT<<<dim3(16, 16, 2), dim3(32, 32)>>>(wq, wk);

    k_gemm_proj<<<dim3(Cc / 128, MROWS / 128, 3), 256, GS_BYTES>>>();
    k_norm<<<MROWS, 256>>>();

    k_state<<<dim3(NCH - 1, Hc, Bc), 256, STATE_SMEM>>>(dlog);
    k_scan<<<dim3(16, 16), 256>>>(dlog);
    k_cattn<<<dim3(NCH, Hc, Bc), 256, CATTN_SMEM>>>(dlog);

    k_gemm_out<<<dim3(Vc / 128, MROWS / 128), 256, GS_BYTES>>>(out, oscal);
}

// round 7
// speedup vs baseline: 5.6279x; 1.4266x over previous
#include <cuda_runtime.h>
#include <cuda_fp16.h>
#include <cstdint>

// Problem constants
#define Bc 4
#define Tc 2048
#define Vc 512
#define Cc 512
#define Hc 4
#define Dc 128
#define NBc 128
#define MROWS (Bc*Tc)    // 8192
#define NCH 32
#define CHL 64

// fp32 scratch
__device__ float g_q[MROWS*Cc];
__device__ float g_k[MROWS*Cc];
__device__ float g_stA[(size_t)16*NCH*Dc*Dc];   // A^T per chunk

// fp16 split scratch (A-operands: hi/lo ; B-operands: single)
__device__ __half g_xh[MROWS*Cc],  g_xl[MROWS*Cc];
__device__ __half g_rh[MROWS*Cc],  g_rl[MROWS*Cc];
__device__ __half g_qnh[MROWS*Cc], g_qnl[MROWS*Cc];
__device__ __half g_knh[MROWS*Cc], g_knl[MROWS*Cc];
__device__ __half g_vsh[MROWS*Cc], g_vsl[MROWS*Cc];
__device__ __half g_wqTh[Cc*Vc];
__device__ __half g_wkTh[Cc*Vc];
__device__ __half g_vwTh[Cc*Vc];
__device__ __half g_owh[Vc*Cc];
__device__ __half g_sTh[(size_t)16*NCH*Dc*Dc];  // T^T single fp16 [bh][c][e][d]

// ===========================================================================
// Helpers
// ===========================================================================
__device__ __forceinline__ uint32_t smem_u32(const void* p) {
    uint32_t a;
    asm("{ .reg .u64 t; cvta.to.shared.u64 t, %1; cvt.u32.u64 %0, t; }"
        : "=r"(a) : "l"(p));
    return a;
}
__device__ __forceinline__ void ldm_x4(uint32_t* r, uint32_t addr) {
    asm volatile("ldmatrix.sync.aligned.m8n8.x4.shared.b16 {%0,%1,%2,%3}, [%4];"
                 : "=r"(r[0]), "=r"(r[1]), "=r"(r[2]), "=r"(r[3]) : "r"(addr));
}
__device__ __forceinline__ void mma_f16(float* c, const uint32_t* a,
                                        const uint32_t* b) {
    asm volatile(
        "mma.sync.aligned.m16n8k16.row.col.f32.f16.f16.f32 "
        "{%0,%1,%2,%3}, {%4,%5,%6,%7}, {%8,%9}, {%0,%1,%2,%3};"
        : "+f"(c[0]), "+f"(c[1]), "+f"(c[2]), "+f"(c[3])
        : "r"(a[0]), "r"(a[1]), "r"(a[2]), "r"(a[3]), "r"(b[0]), "r"(b[1]));
}
__device__ __forceinline__ void cp16(uint32_t dst, const void* src) {
    asm volatile("cp.async.cg.shared.global [%0], [%1], 16;"
                 :: "r"(dst), "l"(src));
}
__device__ __forceinline__ void cp_commit() {
    asm volatile("cp.async.commit_group;");
}
template <int N>
__device__ __forceinline__ void cp_wait() {
    asm volatile("cp.async.wait_group %0;" :: "n"(N));
}
__device__ __forceinline__ void split2(float v, __half& h, __half& l) {
    h = __float2half_rn(v);
    l = __float2half_rn(v - __half2float(h));
}

// ===========================================================================
// 2-pass split-fp16 warp-MMA GEMM: C[128,128] = A[M,512]@B[N,512]^T
// A split hi/lo, B single. K-slab 64 (pitch 144B), double-buffered, 3 slabs.
// ===========================================================================
#define GSLAB 18432                 // 128 rows * 144B
#define GBUF  (3 * GSLAB)           // 55296
#define GS_BYTES (2 * GBUF)         // 110592

__device__ __forceinline__ void gemm_mma_tile(
    const __half* __restrict__ Ah, const __half* __restrict__ Al,
    const __half* __restrict__ Bh,
    float* __restrict__ Cp, __half* __restrict__ Oh, __half* __restrict__ Ol,
    float alpha, int tm, int tn)
{
    extern __shared__ __align__(16) char smc[];
    const int tid = threadIdx.x, lane = tid & 31, wid = tid >> 5;
    const int wm = wid >> 2, wn = wid & 3;
    const uint32_t sb = smem_u32(smc);

    float acc[4][4][4];
#pragma unroll
    for (int i = 0; i < 4; i++)
#pragma unroll
        for (int j = 0; j < 4; j++)
#pragma unroll
            for (int q = 0; q < 4; q++) acc[i][j][q] = 0.f;

    const __half* bases[3];
    bases[0] = Ah + ((size_t)tm * 128) * 512;
    bases[1] = Al + ((size_t)tm * 128) * 512;
    bases[2] = Bh + ((size_t)tn * 128) * 512;

    auto issue = [&](int c, int buf) {
        const uint32_t bb = sb + buf * GBUF;
#pragma unroll
        for (int s = 0; s < 3; s++) {
            const __half* src = bases[s] + c * 64;
#pragma unroll
            for (int i = 0; i < 4; i++) {
                const int idx = tid + 256 * i;
                const int row = idx >> 3, q = idx & 7;
                cp16(bb + s * GSLAB + row * 144 + q * 16,
                     src + (size_t)row * 512 + q * 8);
            }
        }
        cp_commit();
    };

    issue(0, 0);
    issue(1, 1);

    const uint32_t a_lrow = wm * 64 + (lane & 15);
    const uint32_t a_koff = (lane >> 4) * 8;
    const uint32_t b_lrow = wn * 32 + (lane & 7) + ((lane >> 4) << 3);
    const uint32_t b_koff = ((lane >> 3) & 1) * 8;

    for (int c = 0; c < 8; c++) {
        if (c == 7) cp_wait<0>(); else cp_wait<1>();
        __syncthreads();
        const uint32_t bb = sb + (c & 1) * GBUF;

#pragma unroll
        for (int ks = 0; ks < 4; ks++) {
            const int k0 = ks * 16;
            uint32_t bh[8];
#pragma unroll
            for (int nf = 0; nf < 2; nf++) {
                const uint32_t boff =
                    (b_lrow + nf * 16) * 144 + (k0 + b_koff) * 2;
                ldm_x4(bh + nf * 4, bb + 2 * GSLAB + boff);
            }
#pragma unroll
            for (int mi = 0; mi < 4; mi++) {
                const uint32_t aoff =
                    (a_lrow + mi * 16) * 144 + (k0 + a_koff) * 2;
                uint32_t ah[4], al[4];
                ldm_x4(ah, bb + 0 * GSLAB + aoff);
                ldm_x4(al, bb + 1 * GSLAB + aoff);
#pragma unroll
                for (int ni = 0; ni < 4; ni++) {
                    mma_f16(acc[mi][ni], ah, bh + ni * 2);
                    mma_f16(acc[mi][ni], al, bh + ni * 2);
                }
            }
        }
        __syncthreads();
        if (c + 2 < 8) issue(c + 2, c & 1);
    }

    const int qr = lane >> 2, qc = lane & 3;
#pragma unroll
    for (int mi = 0; mi < 4; mi++) {
#pragma unroll
        for (int ni = 0; ni < 4; ni++) {
            const int m = tm * 128 + wm * 64 + mi * 16 + qr;
            const int n = tn * 128 + wn * 32 + ni * 8 + qc * 2;
            float o0 = acc[mi][ni][0] * alpha, o1 = acc[mi][ni][1] * alpha;
            float o2 = acc[mi][ni][2] * alpha, o3 = acc[mi][ni][3] * alpha;
            if (Cp) {
                float2 v0, v1;
                v0.x = o0; v0.y = o1; v1.x = o2; v1.y = o3;
                *(float2*)(Cp + (size_t)m * 512 + n)       = v0;
                *(float2*)(Cp + (size_t)(m + 8) * 512 + n) = v1;
            } else {
                __half h0, l0, h1, l1, h2, l2, h3, l3;
                split2(o0, h0, l0); split2(o1, h1, l1);
                split2(o2, h2, l2); split2(o3, h3, l3);
                __half2 p;
                p.x = h0; p.y = h1;
                *(__half2*)(Oh + (size_t)m * 512 + n) = p;
                p.x = l0; p.y = l1;
                *(__half2*)(Ol + (size_t)m * 512 + n) = p;
                p.x = h2; p.y = h3;
                *(__half2*)(Oh + (size_t)(m + 8) * 512 + n) = p;
                p.x = l2; p.y = l3;
                *(__half2*)(Ol + (size_t)(m + 8) * 512 + n) = p;
            }
        }
    }
}

__global__ void __launch_bounds__(256) k_gemm_proj()
{
    if (blockIdx.z == 0)
        gemm_mma_tile(g_xh, g_xl, g_wqTh, g_q, nullptr, nullptr, 1.f,
                      blockIdx.y, blockIdx.x);
    else if (blockIdx.z == 1)
        gemm_mma_tile(g_xh, g_xl, g_wkTh, g_k, nullptr, nullptr, 1.f,
                      blockIdx.y, blockIdx.x);
    else
        gemm_mma_tile(g_xh, g_xl, g_vwTh, nullptr, g_vsh, g_vsl, 1.f,
                      blockIdx.y, blockIdx.x);
}

__global__ void __launch_bounds__(256) k_gemm_out(float* __restrict__ out,
                                                  const float* __restrict__ os)
{
    gemm_mma_tile(g_rh, g_rl, g_owh, out, nullptr, nullptr, __ldg(os),
                  blockIdx.y, blockIdx.x);
}

// ===========================================================================
// Split x -> fp16 hi/lo
// ===========================================================================
__global__ void __launch_bounds__(256) k_split(const float* __restrict__ in)
{
    int i = blockIdx.x * 256 + threadIdx.x;
    float4 v = ((const float4*)in)[i];
    __half h0, h1, h2, h3, l0, l1, l2, l3;
    split2(v.x, h0, l0); split2(v.y, h1, l1);
    split2(v.z, h2, l2); split2(v.w, h3, l3);
    __half2 p;
    p.x = h0; p.y = h1; ((__half2*)g_xh)[2 * i]     = p;
    p.x = h2; p.y = h3; ((__half2*)g_xh)[2 * i + 1] = p;
    p.x = l0; p.y = l1; ((__half2*)g_xl)[2 * i]     = p;
    p.x = l2; p.y = l3; ((__half2*)g_xl)[2 * i + 1] = p;
}

// Transpose 512x512 weights -> single fp16 (wq, wk)
__global__ void __launch_bounds__(1024) k_splitT(const float* __restrict__ wq,
                                                 const float* __restrict__ wk)
{
    __shared__ float t[32][33];
    const float* in = (blockIdx.z == 0) ? wq : wk;
    __half* oh = (blockIdx.z == 0) ? g_wqTh : g_wkTh;
    const int x = blockIdx.x * 32 + threadIdx.x;
    const int y = blockIdx.y * 32 + threadIdx.y;
    t[threadIdx.y][threadIdx.x] = in[y * 512 + x];
    __syncthreads();
    const float v = t[threadIdx.x][threadIdx.y];
    const int ox = blockIdx.y * 32 + threadIdx.x;
    const int oy = blockIdx.x * 32 + threadIdx.y;
    oh[oy * 512 + ox] = __float2half_rn(v);
}

// ===========================================================================
// k_weights: z=0: vwT[c][v] = vc @ basis^T ; z=1: ow[v][c] = basis @ oc^T
// fp32 compute, single-fp16 epilogue. M=N=512, K=128 (NT).
// ===========================================================================
__global__ void __launch_bounds__(256) k_weights(
    const float* __restrict__ basis, const float* __restrict__ vc,
    const float* __restrict__ oc)
{
    __shared__ float As[8][132];
    __shared__ float Bs[8][132];
    const int z = blockIdx.z;
    const float* A = z ? basis : vc;
    const float* B = z ? oc : basis;
    __half* Oh = z ? g_owh : g_vwTh;
    const int bx = blockIdx.x, by = blockIdx.y;
    const int tid = threadIdx.x;
    const int tx = tid & 15, ty = tid >> 4;

    float acc[8][8];
#pragma unroll
    for (int i = 0; i < 8; i++)
#pragma unroll
        for (int j = 0; j < 8; j++) acc[i][j] = 0.f;

    const float* Ab = A + (size_t)(by * 128) * NBc;

    for (int k0 = 0; k0 < NBc; k0 += 8) {
        {
            const int ar = tid >> 1, ac = (tid & 1) * 4;
            float4 v = *(const float4*)(Ab + (size_t)ar * NBc + k0 + ac);
            As[ac + 0][ar] = v.x; As[ac + 1][ar] = v.y;
            As[ac + 2][ar] = v.z; As[ac + 3][ar] = v.w;
        }
        {
            const int br = tid >> 1, bc = (tid & 1) * 4;
            float4 v = *(const float4*)(B + (size_t)(bx * 128 + br) * NBc + k0 + bc);
            Bs[bc + 0][br] = v.x; Bs[bc + 1][br] = v.y;
            Bs[bc + 2][br] = v.z; Bs[bc + 3][br] = v.w;
        }
        __syncthreads();

#pragma unroll
        for (int kk = 0; kk < 8; kk++) {
            float a[8], bf[8];
            *(float4*)(a)     = *(const float4*)&As[kk][ty * 8];
            *(float4*)(a + 4) = *(const float4*)&As[kk][ty * 8 + 4];
            *(float4*)(bf)     = *(const float4*)&Bs[kk][tx * 8];
            *(float4*)(bf + 4) = *(const float4*)&Bs[kk][tx * 8 + 4];
#pragma unroll
            for (int i = 0; i < 8; i++)
#pragma unroll
                for (int j = 0; j < 8; j++) acc[i][j] += a[i] * bf[j];
        }
        __syncthreads();
    }

#pragma unroll
    for (int i = 0; i < 8; i++) {
        const size_t rowb = (size_t)(by * 128 + ty * 8 + i) * 512 + bx * 128 + tx * 8;
#pragma unroll
        for (int j = 0; j < 8; j += 2) {
            __half2 p;
            p.x = __float2half_rn(acc[i][j]);
            p.y = __float2half_rn(acc[i][j + 1]);
            *(__half2*)(Oh + rowb + j) = p;
        }
    }
}

// L2-normalize rows of g_q/g_k, write fp16 splits
__global__ void __launch_bounds__(256) k_norm()
{
    const int row = blockIdx.x;
    const float* q = g_q + (size_t)row * Cc;
    const float* k = g_k + (size_t)row * Cc;
    const int t = threadIdx.x;
    float q0 = q[t], q1 = q[t + 256];
    float k0 = k[t], k1 = k[t + 256];
    float sq = q0 * q0 + q1 * q1;
    float sk = k0 * k0 + k1 * k1;
#pragma unroll
    for (int off = 16; off; off >>= 1) {
        sq += __shfl_xor_sync(0xffffffffu, sq, off);
        sk += __shfl_xor_sync(0xffffffffu, sk, off);
    }
    __shared__ float rq[8], rk[8];
    __shared__ float inv[2];
    const int w = t >> 5, l = t & 31;
    if (l == 0) { rq[w] = sq; rk[w] = sk; }
    __syncthreads();
    if (t == 0) {
        float a = 0.f, cc = 0.f;
#pragma unroll
        for (int i = 0; i < 8; i++) { a += rq[i]; cc += rk[i]; }
        inv[0] = 1.f / fmaxf(sqrtf(a), 1e-12f);
        inv[1] = 1.f / fmaxf(sqrtf(cc), 1e-12f);
    }
    __syncthreads();
    const float iq = inv[0], ik = inv[1];
    __half h, lo;
    const size_t b = (size_t)row * Cc;
    split2(q0 * iq, h, lo); g_qnh[b + t] = h;       g_qnl[b + t] = lo;
    split2(q1 * iq, h, lo); g_qnh[b + t + 256] = h; g_qnl[b + t + 256] = lo;
    split2(k0 * ik, h, lo); g_knh[b + t] = h;       g_knl[b + t] = lo;
    split2(k1 * ik, h, lo); g_knh[b + t + 256] = h; g_knl[b + t + 256] = lo;
}

// ===========================================================================
// Phase A (MMA): A^T_c[e][d] = sum_j V[j][e] * (d^j K[j][d])
// A = V^T hi/lo ; B = decayed K^T single. 2 passes.
// ===========================================================================
#define ST_K  0
#define ST_VH 18432
#define ST_VL 36864
#define STATE_SMEM 55296

__global__ void __launch_bounds__(256) k_state(const float* __restrict__ dlog)
{
    extern __shared__ __align__(16) char sm[];
    const int c = blockIdx.x + 1, h = blockIdx.y, b = blockIdx.z;
    const int tid = threadIdx.x, lane = tid & 31, wid = tid >> 5;
    const float dec = 1.f / (1.f + expf(-dlog[h]));
    const float l2d = log2f(dec);
    const size_t gb = ((size_t)b * Tc + c * CHL) * Cc + h * Dc;

#pragma unroll
    for (int i = 0; i < 32; i++) {
        const int idx = tid + 256 * i;
        const int d = idx & 127, j = idx >> 7;
        const float kv = __half2float(g_knh[gb + (size_t)j * Cc + d]) +
                         __half2float(g_knl[gb + (size_t)j * Cc + d]);
        *(__half*)(sm + ST_K + d * 144 + j * 2) =
            __float2half_rn(kv * exp2f(l2d * (float)j));
        *(__half*)(sm + ST_VH + d * 144 + j * 2) =
            g_vsh[gb + (size_t)j * Cc + d];
        *(__half*)(sm + ST_VL + d * 144 + j * 2) =
            g_vsl[gb + (size_t)j * Cc + d];
    }
    __syncthreads();

    const int wm = wid >> 2, wn = wid & 3;
    const uint32_t sb = smem_u32(sm);
    const uint32_t a_lrow = wm * 64 + (lane & 15);
    const uint32_t a_koff = (lane >> 4) * 8;
    const uint32_t b_lrow = wn * 32 + (lane & 7) + ((lane >> 4) << 3);
    const uint32_t b_koff = ((lane >> 3) & 1) * 8;

    float acc[4][4][4];
#pragma unroll
    for (int i = 0; i < 4; i++)
#pragma unroll
        for (int j = 0; j < 4; j++)
#pragma unroll
            for (int q = 0; q < 4; q++) acc[i][j][q] = 0.f;

#pragma unroll
    for (int ks = 0; ks < 4; ks++) {
        const int k0 = ks * 16;
        uint32_t kh[8];
#pragma unroll
        for (int nf = 0; nf < 2; nf++) {
            const uint32_t boff = (b_lrow + nf * 16) * 144 + (k0 + b_koff) * 2;
            ldm_x4(kh + nf * 4, sb + ST_K + boff);
        }
#pragma unroll
        for (int mi = 0; mi < 4; mi++) {
            uint32_t vh[4], vl[4];
            const uint32_t aoff = (a_lrow + mi * 16) * 144 + (k0 + a_koff) * 2;
            ldm_x4(vh, sb + ST_VH + aoff);
            ldm_x4(vl, sb + ST_VL + aoff);
#pragma unroll
            for (int ni = 0; ni < 4; ni++) {
                mma_f16(acc[mi][ni], vh, kh + ni * 2);
                mma_f16(acc[mi][ni], vl, kh + ni * 2);
            }
        }
    }

    float* dst = g_stA + ((size_t)(b * Hc + h) * NCH + c) * (Dc * Dc);
    const int qr = lane >> 2, qc = lane & 3;
#pragma unroll
    for (int mi = 0; mi < 4; mi++) {
#pragma unroll
        for (int ni = 0; ni < 4; ni++) {
            const int m = wm * 64 + mi * 16 + qr;
            const int n = wn * 32 + ni * 8 + qc * 2;
            float2 v0, v1;
            v0.x = acc[mi][ni][0]; v0.y = acc[mi][ni][1];
            v1.x = acc[mi][ni][2]; v1.y = acc[mi][ni][3];
            *(float2*)(dst + (size_t)m * Dc + n)       = v0;
            *(float2*)(dst + (size_t)(m + 8) * Dc + n) = v1;
        }
    }
}

// ===========================================================================
// Phase B: backward scan on A^T, writes single-fp16 T^T.
// ===========================================================================
__global__ void __launch_bounds__(256) k_scan(const float* __restrict__ dlog)
{
    const int bh = blockIdx.x;
    const int h = bh & (Hc - 1);
    const int idx4 = blockIdx.y * 256 + threadIdx.x;   // 0..4095
    const float dec = 1.f / (1.f + expf(-dlog[h]));
    const float dL = exp2f(log2f(dec) * (float)CHL);

    float4 run = make_float4(0.f, 0.f, 0.f, 0.f);
    for (int c = NCH - 2; c >= 0; c--) {
        const float4* A =
            (const float4*)(g_stA + ((size_t)bh * NCH + c + 1) * (Dc * Dc));
        float4 a = A[idx4];
        run.x = a.x + dL * run.x;
        run.y = a.y + dL * run.y;
        run.z = a.z + dL * run.z;
        run.w = a.w + dL * run.w;
        const size_t o = ((size_t)bh * NCH + c) * (Dc * Dc) + (size_t)idx4 * 4;
        __half2 p;
        p.x = __float2half_rn(run.x); p.y = __float2half_rn(run.y);
        *(__half2*)(g_sTh + o) = p;
        p.x = __float2half_rn(run.z); p.y = __float2half_rn(run.w);
        *(__half2*)(g_sTh + o + 2) = p;
    }
}

// ===========================================================================
// Phase C (MMA): intra masked attention + inter Q@T^T (T single fp16).
// ===========================================================================
#define CQ_H 0
#define CQ_L 17408
#define CK   34816
#define CV   52224
#define CS_H 70656
#define CS_L 79872
#define CT   89088
#define CATTN_SMEM 123904

__global__ void __launch_bounds__(256) k_cattn(const float* __restrict__ dlog)
{
    extern __shared__ __align__(16) char sm[];
    const int c = blockIdx.x, h = blockIdx.y, b = blockIdx.z;
    const int tid = threadIdx.x, lane = tid & 31, wid = tid >> 5;
    const int wm = wid >> 2, wn = wid & 3;
    const float dec = 1.f / (1.f + expf(-dlog[h]));
    const float l2d = log2f(dec);
    const size_t gb = ((size_t)b * Tc + c * CHL) * Cc + h * Dc;
    const uint32_t sb = smem_u32(sm);

    // Prefetch full T^T (single fp16) with cp.async
    if (c < NCH - 1) {
        const __half* Th = g_sTh + ((size_t)(b * Hc + h) * NCH + c) * (Dc * Dc);
#pragma unroll
        for (int i = 0; i < 8; i++) {
            const int idx = tid + 256 * i;           // 0..2047
            const int e = idx >> 4, q = idx & 15;
            cp16(sb + CT + e * 272 + q * 16, Th + (size_t)e * 128 + q * 8);
        }
    }
    cp_commit();

    // Q hi/lo, K single tiles 64x128 pitch 272B
    {
        const uint4* s0 = (const uint4*)(g_qnh + gb);
        const uint4* s1 = (const uint4*)(g_qnl + gb);
        const uint4* s2 = (const uint4*)(g_knh + gb);
#pragma unroll
        for (int i = 0; i < 4; i++) {
            const int idx = tid + 256 * i;
            const int row = idx >> 4, q = idx & 15;
            const size_t so = (size_t)row * 64 + q;
            const uint32_t doff = row * 272 + q * 16;
            *(uint4*)(sm + CQ_H + doff) = s0[so];
            *(uint4*)(sm + CQ_L + doff) = s1[so];
            *(uint4*)(sm + CK   + doff) = s2[so];
        }
    }
    // Transposed V (single): VT[d][j] pitch 144B
#pragma unroll
    for (int i = 0; i < 32; i++) {
        const int idx = tid + 256 * i;
        const int d = idx & 127, j = idx >> 7;
        *(__half*)(sm + CV + d * 144 + j * 2) = g_vsh[gb + (size_t)j * Cc + d];
    }
    __syncthreads();

    const uint32_t a_koff = (lane >> 4) * 8;
    const uint32_t b_koff = ((lane >> 3) & 1) * 8;
    const uint32_t aQ_row = wm * 32 + (lane & 15);
    const uint32_t bS_row = wn * 16 + (lane & 7) + ((lane >> 4) << 3);
    const uint32_t bO_row = wn * 32 + (lane & 7) + ((lane >> 4) << 3);
    const int qr = lane >> 2, qc = lane & 3;

    // ---- intra: S = Q K^T (2 passes) ----
    float accS[2][2][4];
#pragma unroll
    for (int i = 0; i < 2; i++)
#pragma unroll
        for (int j = 0; j < 2; j++)
#pragma unroll
            for (int q = 0; q < 4; q++) accS[i][j][q] = 0.f;

#pragma unroll
    for (int ks = 0; ks < 8; ks++) {
        const int k0 = ks * 16;
        uint32_t kh[4];
        const uint32_t boff = bS_row * 272 + (k0 + b_koff) * 2;
        ldm_x4(kh, sb + CK + boff);
#pragma unroll
        for (int mi = 0; mi < 2; mi++) {
            uint32_t qh[4], ql[4];
            const uint32_t aoff = (aQ_row + mi * 16) * 272 + (k0 + a_koff) * 2;
            ldm_x4(qh, sb + CQ_H + aoff);
            ldm_x4(ql, sb + CQ_L + aoff);
#pragma unroll
            for (int ni = 0; ni < 2; ni++) {
                mma_f16(accS[mi][ni], qh, kh + ni * 2);
                mma_f16(accS[mi][ni], ql, kh + ni * 2);
            }
        }
    }

    // mask + split-store S (fp16 hi/lo)
#pragma unroll
    for (int mi = 0; mi < 2; mi++) {
#pragma unroll
        for (int ni = 0; ni < 2; ni++) {
#pragma unroll
            for (int q = 0; q < 4; q++) {
                const int il = wm * 32 + mi * 16 + qr + (q >> 1) * 8;
                const int jl = wn * 16 + ni * 8 + qc * 2 + (q & 1);
                float s = 0.f;
                if (jl > il)
                    s = accS[mi][ni][q] * exp2f(l2d * (float)(jl - il - 1));
                __half hh, ll;
                split2(s, hh, ll);
                *(__half*)(sm + CS_H + il * 144 + jl * 2) = hh;
                *(__half*)(sm + CS_L + il * 144 + jl * 2) = ll;
            }
        }
    }
    cp_wait<0>();
    __syncthreads();

    // ---- O accumulators ----
    float acc[2][4][4], accI[2][4][4];
#pragma unroll
    for (int i = 0; i < 2; i++)
#pragma unroll
        for (int j = 0; j < 4; j++)
#pragma unroll
            for (int q = 0; q < 4; q++) { acc[i][j][q] = 0.f; accI[i][j][q] = 0.f; }

    // intra SV: S hi/lo x V single, K=64
#pragma unroll
    for (int ks = 0; ks < 4; ks++) {
        const int k0 = ks * 16;
        uint32_t vh[8];
#pragma unroll
        for (int nf = 0; nf < 2; nf++) {
            const uint32_t boff = (bO_row + nf * 16) * 144 + (k0 + b_koff) * 2;
            ldm_x4(vh + nf * 4, sb + CV + boff);
        }
#pragma unroll
        for (int mi = 0; mi < 2; mi++) {
            uint32_t sh[4], sl[4];
            const uint32_t aoff = (aQ_row + mi * 16) * 144 + (k0 + a_koff) * 2;
            ldm_x4(sh, sb + CS_H + aoff);
            ldm_x4(sl, sb + CS_L + aoff);
#pragma unroll
            for (int ni = 0; ni < 4; ni++) {
                mma_f16(acc[mi][ni], sh, vh + ni * 2);
                mma_f16(acc[mi][ni], sl, vh + ni * 2);
            }
        }
    }

    // inter: O_i += Q @ T^T (Q hi/lo x T single), K=128
    if (c < NCH - 1) {
#pragma unroll
        for (int ks = 0; ks < 8; ks++) {
            const int k0 = ks * 16;
            uint32_t th[8];
#pragma unroll
            for (int nf = 0; nf < 2; nf++) {
                const uint32_t boff =
                    (bO_row + nf * 16) * 272 + (k0 + b_koff) * 2;
                ldm_x4(th + nf * 4, sb + CT + boff);
            }
#pragma unroll
            for (int mi = 0; mi < 2; mi++) {
                uint32_t qh[4], ql[4];
                const uint32_t aoff =
                    (aQ_row + mi * 16) * 272 + (k0 + a_koff) * 2;
                ldm_x4(qh, sb + CQ_H + aoff);
                ldm_x4(ql, sb + CQ_L + aoff);
#pragma unroll
                for (int ni = 0; ni < 4; ni++) {
                    mma_f16(accI[mi][ni], qh, th + ni * 2);
                    mma_f16(accI[mi][ni], ql, th + ni * 2);
                }
            }
        }
    }

    // epilogue: O = acc + f(row) * accI -> fp16 split write g_rh/g_rl
#pragma unroll
    for (int mi = 0; mi < 2; mi++) {
        const int r0 = wm * 32 + mi * 16 + qr;
        const float f0 = exp2f(l2d * (float)(63 - r0));
        const float f1 = exp2f(l2d * (float)(63 - (r0 + 8)));
#pragma unroll
        for (int ni = 0; ni < 4; ni++) {
            const int col = wn * 32 + ni * 8 + qc * 2;
            const size_t a0 = gb + (size_t)r0 * Cc + col;
            const size_t a1 = gb + (size_t)(r0 + 8) * Cc + col;
            float o0 = acc[mi][ni][0] + f0 * accI[mi][ni][0];
            float o1 = acc[mi][ni][1] + f0 * accI[mi][ni][1];
            float o2 = acc[mi][ni][2] + f1 * accI[mi][ni][2];
            float o3 = acc[mi][ni][3] + f1 * accI[mi][ni][3];
            __half h0, l0, h1, l1, h2, l2, h3, l3;
            split2(o0, h0, l0); split2(o1, h1, l1);
            split2(o2, h2, l2); split2(o3, h3, l3);
            __half2 p;
            p.x = h0; p.y = h1; *(__half2*)(g_rh + a0) = p;
            p.x = l0; p.y = l1; *(__half2*)(g_rl + a0) = p;
            p.x = h2; p.y = h3; *(__half2*)(g_rh + a1) = p;
            p.x = l2; p.y = l3; *(__half2*)(g_rl + a1) = p;
        }
    }
}

extern "C" void kernel_launch(void* const* d_in, const int* in_sizes, int n_in,
                              void* d_out, int out_size)
{
    const float* x     = (const float*)d_in[0];
    const float* basis = (const float*)d_in[1];
    const float* wq    = (const float*)d_in[2];
    const float* wk    = (const float*)d_in[3];
    const float* vc    = (const float*)d_in[4];
    const float* oc    = (const float*)d_in[5];
    const float* dlog  = (const float*)d_in[6];
    const float* oscal = (const float*)d_in[7];
    float* out = (float*)d_out;

    (void)in_sizes; (void)n_in; (void)out_size;

    cudaFuncSetAttribute(k_state, cudaFuncAttributeMaxDynamicSharedMemorySize,
                         STATE_SMEM);
    cudaFuncSetAttribute(k_cattn, cudaFuncAttributeMaxDynamicSharedMemorySize,
                         CATTN_SMEM);
    cudaFuncSetAttribute(k_gemm_proj, cudaFuncAttributeMaxDynamicSharedMemorySize,
                         GS_BYTES);
    cudaFuncSetAttribute(k_gemm_out, cudaFuncAttributeMaxDynamicSharedMemorySize,
                         GS_BYTES);

    k_weights<<<dim3(4, 4, 2), 256>>>(basis, vc, oc);
    k_split<<<MROWS * Cc / 4 / 256, 256>>>(x);
    k_splitT<<<dim3(16, 16, 2), dim3(32, 32)>>>(wq, wk);

    k_gemm_proj<<<dim3(Cc / 128, MROWS / 128, 3), 256, GS_BYTES>>>();
    k_norm<<<MROWS, 256>>>();

    k_state<<<dim3(NCH - 1, Hc, Bc), 256, STATE_SMEM>>>(dlog);
    k_scan<<<dim3(16, 16), 256>>>(dlog);
    k_cattn<<<dim3(NCH, Hc, Bc), 256, CATTN_SMEM>>>(dlog);

    k_gemm_out<<<dim3(Vc / 128, MROWS / 128), 256, GS_BYTES>>>(out, oscal);
}